// round 15
// baseline (speedup 1.0000x reference)
#include <cuda_runtime.h>
#include <cuda_bf16.h>
#include <math.h>
#include <cstdint>

#define NNODES 4096
#define FEAT   128
#define NEDGES 65536
#define NG     317
#define NB     64
#define NC     64
#define HID    512
#define DH     64
#define NROWS  (NG*NB)
#define FFD    1024
#define MTILES 159
#define PADROWS (MTILES*128)

typedef unsigned long long u64;

// ---------------- f32x2 helpers ----------------
__device__ __forceinline__ u64 dup2(float x) {
    u64 r; asm("mov.b64 %0,{%1,%1};" : "=l"(r) : "f"(x)); return r;
}
__device__ __forceinline__ u64 ffma2(u64 a, u64 b, u64 c) {
    u64 d; asm("fma.rn.f32x2 %0,%1,%2,%3;" : "=l"(d) : "l"(a), "l"(b), "l"(c)); return d;
}
__device__ __forceinline__ float2 up2(u64 v) {
    float2 f; asm("mov.b64 {%0,%1},%2;" : "=f"(f.x), "=f"(f.y) : "l"(v)); return f;
}

// ---------------- mma.sync / cp.async helpers ----------------
__device__ __forceinline__ uint32_t smem_u32(const void* p) {
    uint32_t a; asm("{ .reg .u64 t; cvta.to.shared.u64 t, %1; cvt.u32.u64 %0, t; }"
                    : "=r"(a) : "l"(p)); return a;
}
__device__ __forceinline__ void ldsm_x4(uint32_t* r, uint32_t addr) {
    asm volatile("ldmatrix.sync.aligned.m8n8.x4.shared.b16 {%0,%1,%2,%3}, [%4];"
        : "=r"(r[0]), "=r"(r[1]), "=r"(r[2]), "=r"(r[3]) : "r"(addr));
}
__device__ __forceinline__ void ldsm_x4_t(uint32_t* r, uint32_t addr) {
    asm volatile("ldmatrix.sync.aligned.m8n8.x4.trans.shared.b16 {%0,%1,%2,%3}, [%4];"
        : "=r"(r[0]), "=r"(r[1]), "=r"(r[2]), "=r"(r[3]) : "r"(addr));
}
__device__ __forceinline__ void mma16816(float* d, const uint32_t* a, const uint32_t* b) {
    asm volatile("mma.sync.aligned.m16n8k16.row.col.f32.bf16.bf16.f32 "
        "{%0,%1,%2,%3}, {%4,%5,%6,%7}, {%8,%9}, {%0,%1,%2,%3};"
        : "+f"(d[0]), "+f"(d[1]), "+f"(d[2]), "+f"(d[3])
        : "r"(a[0]), "r"(a[1]), "r"(a[2]), "r"(a[3]), "r"(b[0]), "r"(b[1]));
}
__device__ __forceinline__ uint32_t pkbf2(float lo, float hi) {
    uint32_t r; asm("cvt.rn.bf16x2.f32 %0, %1, %2;" : "=r"(r) : "f"(hi), "f"(lo)); return r;
}
__device__ __forceinline__ void cpa16(uint32_t dst, const void* src) {
    asm volatile("cp.async.ca.shared.global [%0], [%1], 16;" :: "r"(dst), "l"(src));
}
#define CP_COMMIT() asm volatile("cp.async.commit_group;" ::: "memory")
#define CP_WAIT(n)  asm volatile("cp.async.wait_group %0;" :: "n"(n) : "memory")
#define BAR_SYNC(id, cnt) asm volatile("bar.sync %0, %1;" :: "r"(id), "r"(cnt) : "memory")
__device__ __forceinline__ void red4(float* p, float4 v) {
    asm volatile("red.global.add.v4.f32 [%0], {%1,%2,%3,%4};"
        :: "l"(p), "f"(v.x), "f"(v.y), "f"(v.z), "f"(v.w) : "memory");
}

// ---------------- scratch ----------------
__device__ float g_deg[NNODES];
__device__ float g_agg[NNODES*FEAT];
__device__ float g_csum[NC*HID];
__device__ float g_meanh[NC*HID];
__device__ float g_h1[NC*FFD];
__device__ float g_h2[NC*HID];
__device__ float g_int[NC*HID];
__device__ float g_affacc[NC];
__device__ int   g_affcnt[NC];
__device__ int   g_cs[NC+1];
__device__ __nv_bfloat16 g_ph[NB*FEAT];
__device__ __nv_bfloat16 g_pl[NB*FEAT];
__device__ __nv_bfloat16 g_Xhi[(size_t)PADROWS*HID];
__device__ __nv_bfloat16 g_Xlo[(size_t)PADROWS*HID];
__device__ __nv_bfloat16 g_Wthi[3*HID*HID];   // [w][n][k]
__device__ __nv_bfloat16 g_Wtlo[3*HID*HID];
__device__ __nv_bfloat16 g_Qhi[(size_t)NROWS*HID];
__device__ __nv_bfloat16 g_Qlo[(size_t)NROWS*HID];
__device__ __nv_bfloat16 g_Khi[(size_t)NROWS*HID];
__device__ __nv_bfloat16 g_Klo[(size_t)NROWS*HID];
__device__ __nv_bfloat16 g_Vhi[(size_t)NROWS*HID];

// ---------------- prep: cvtW (blocks 0..767) + init (768..1023) ----------------
__global__ void __launch_bounds__(256) k_prep(const int* __restrict__ counts,
                                              const float* __restrict__ Wq,
                                              const float* __restrict__ Wk,
                                              const float* __restrict__ Wv) {
    int bid = blockIdx.x;
    if (bid < 768) {
        __shared__ float tile[32][33];
        int w = bid / 256;
        int rem = bid % 256;
        int kb = (rem / 16) * 32, nb = (rem % 16) * 32;
        const float* W = (w == 0) ? Wq : (w == 1) ? Wk : Wv;
        int tx = threadIdx.x & 31, ty = threadIdx.x >> 5;
        #pragma unroll
        for (int i = 0; i < 4; i++)
            tile[ty + i*8][tx] = W[(size_t)(kb + ty + i*8)*HID + nb + tx];
        __syncthreads();
        #pragma unroll
        for (int i = 0; i < 4; i++) {
            int n = nb + ty + i*8, k = kb + tx;
            float v = tile[tx][ty + i*8];
            __nv_bfloat16 h = __float2bfloat16(v);
            size_t o = (size_t)w*HID*HID + (size_t)n*HID + k;
            g_Wthi[o] = h;
            g_Wtlo[o] = __float2bfloat16(v - __bfloat162float(h));
        }
    } else {
        int i = (bid - 768) * 256 + threadIdx.x;
        const int nt = 256*256;
        if (i < NNODES) g_deg[i] = 0.f;
        for (int j = i; j < NNODES*FEAT; j += nt) g_agg[j] = 0.f;
        if (i < NC*HID) { g_csum[i] = 0.f; g_meanh[i] = 0.f; g_h2[i] = 0.f; }
        for (int j = i; j < NC*FFD; j += nt) g_h1[j] = 0.f;
        if (i < NC) { g_affacc[i] = 0.f; g_affcnt[i] = 0; }
        for (int j = i; j < (PADROWS - NROWS) * HID; j += nt) {
            g_Xhi[(size_t)NROWS*HID + j] = __float2bfloat16(0.f);
            g_Xlo[(size_t)NROWS*HID + j] = __float2bfloat16(0.f);
        }
        if (i == 0) {
            int s = 0;
            for (int c = 0; c < NC; c++) { g_cs[c] = s; s += counts[c]; }
            g_cs[NC] = s;
        }
    }
}

// ---------------- edge aggregation ----------------
__global__ void k_edges(const float* __restrict__ x, const int* __restrict__ ei) {
    int t = blockIdx.x * blockDim.x + threadIdx.x;
    int e = t >> 5, lane = t & 31;
    if (e >= NEDGES) return;
    int s = ei[e], d = ei[NEDGES + e];
    float4 v = *(const float4*)(x + (size_t)s*FEAT + lane*4);
    red4(g_agg + (size_t)d*FEAT + lane*4, v);
    if (lane == 0) atomicAdd(g_deg + d, 1.f);
}

// ---------------- per-graph mean pool -> bf16 hi/lo ----------------
__global__ void k_pool(const float* __restrict__ x) {
    int g = blockIdx.x, f = threadIdx.x;
    float s = 0.f;
    for (int n = g*64; n < g*64 + 64; n++) {
        float inv = 1.f / fmaxf(g_deg[n], 1.f);
        s += x[(size_t)n*FEAT + f] + g_agg[(size_t)n*FEAT + f] * inv;
    }
    s *= (1.f/64.f);
    __nv_bfloat16 h = __float2bfloat16(s);
    g_ph[g*FEAT + f] = h;
    g_pl[g*FEAT + f] = __float2bfloat16(s - __bfloat162float(h));
}

// ---------------- per-gene GEMM via mma.sync bf16, n-block=64 ----------------
#define GAH 0
#define GAL 16384
#define GBH 32768
#define GBL 49152
#define GENE_SMEM 65536

__global__ void __launch_bounds__(256) k_gene_mma(const float* __restrict__ gW,
                                                  const float* __restrict__ gb) {
    extern __shared__ char smem[];
    uint32_t sb = smem_u32(smem);
    int tid = threadIdx.x, wid = tid >> 5, lane = tid & 31;
    int g = blockIdx.x, n0 = blockIdx.y * 64;
    int wr = wid & 3, wc = wid >> 2;

    for (int u = tid; u < 1024; u += 256) {
        int row = u >> 4, c = u & 15;
        uint32_t dst = (uint32_t)(((row << 4) | (c ^ (row & 7))) << 4);
        int go = row*FEAT + c*8;
        cpa16(sb + GAH + dst, g_ph + go);
        cpa16(sb + GAL + dst, g_pl + go);
    }
    CP_COMMIT();
    for (int u = tid; u < 1024; u += 256) {
        int row = u >> 3, c = u & 7;
        const float* src = gW + (size_t)g*FEAT*HID + (size_t)row*HID + n0 + c*8;
        float4 f0 = *(const float4*)src;
        float4 f1 = *(const float4*)(src + 4);
        float v[8] = {f0.x,f0.y,f0.z,f0.w,f1.x,f1.y,f1.z,f1.w};
        float hh[8];
        #pragma unroll
        for (int p = 0; p < 8; p++) hh[p] = __bfloat162float(__float2bfloat16(v[p]));
        uint4 hv, lv;
        hv.x = pkbf2(v[0],v[1]); hv.y = pkbf2(v[2],v[3]);
        hv.z = pkbf2(v[4],v[5]); hv.w = pkbf2(v[6],v[7]);
        lv.x = pkbf2(v[0]-hh[0],v[1]-hh[1]); lv.y = pkbf2(v[2]-hh[2],v[3]-hh[3]);
        lv.z = pkbf2(v[4]-hh[4],v[5]-hh[5]); lv.w = pkbf2(v[6]-hh[6],v[7]-hh[7]);
        uint32_t dst = (uint32_t)(((row << 3) | (c ^ (row & 7))) << 4);
        *(uint4*)(smem + GBH + dst) = hv;
        *(uint4*)(smem + GBL + dst) = lv;
    }
    CP_WAIT(0);
    __syncthreads();

    float acc[4][4];
    #pragma unroll
    for (int t = 0; t < 4; t++)
        #pragma unroll
        for (int j = 0; j < 4; j++) acc[t][j] = 0.f;

    #pragma unroll
    for (int s = 0; s < 8; s++) {
        int arow = wr*16 + (lane & 15);
        int ac   = s*2 + (lane >> 4);
        uint32_t aoff = (uint32_t)(((arow << 4) | (ac ^ (arow & 7))) << 4);
        uint32_t ah[4], al[4];
        ldsm_x4(ah, sb + GAH + aoff);
        ldsm_x4(al, sb + GAL + aoff);
        int grp = lane >> 3;
        int vrow = s*16 + (lane & 7) + ((grp & 1) << 3);
        #pragma unroll
        for (int dblk = 0; dblk < 2; dblk++) {
            int vch = wc*4 + dblk*2 + (grp >> 1);
            uint32_t voff = (uint32_t)(((vrow << 3) | (vch ^ (vrow & 7))) << 4);
            uint32_t vbh[4], vbl[4];
            ldsm_x4_t(vbh, sb + GBH + voff);
            ldsm_x4_t(vbl, sb + GBL + voff);
            mma16816(acc[dblk*2],   ah, &vbh[0]);
            mma16816(acc[dblk*2],   ah, &vbl[0]);
            mma16816(acc[dblk*2],   al, &vbh[0]);
            mma16816(acc[dblk*2+1], ah, &vbh[2]);
            mma16816(acc[dblk*2+1], ah, &vbl[2]);
            mma16816(acc[dblk*2+1], al, &vbh[2]);
        }
    }
    int row0 = wr*16 + (lane >> 2);
    int cb = n0 + wc*32 + 2*(lane & 3);
    #pragma unroll
    for (int n8 = 0; n8 < 4; n8++) {
        int col = cb + n8*8;
        float b0 = gb[(size_t)g*HID + col], b1 = gb[(size_t)g*HID + col + 1];
        #pragma unroll
        for (int half = 0; half < 2; half++) {
            int row = g*64 + row0 + half*8;
            float v0 = fmaxf(acc[n8][half*2+0] + b0, 0.f);
            float v1 = fmaxf(acc[n8][half*2+1] + b1, 0.f);
            float h0 = __bfloat162float(__float2bfloat16(v0));
            float h1 = __bfloat162float(__float2bfloat16(v1));
            *(uint32_t*)(g_Xhi + (size_t)row*HID + col) = pkbf2(v0, v1);
            *(uint32_t*)(g_Xlo + (size_t)row*HID + col) = pkbf2(v0 - h0, v1 - h1);
        }
    }
}

// ---------------- fused Q+K+V GEMM, compensated (hi/lo W), double-buffered ----------------
#define QBUF 81920
#define QAH 0
#define QAL 16384
#define QB0 32768
#define QKV_SMEM (2*QBUF)

__global__ void __launch_bounds__(256, 1) k_qkv_mma(
        const float* __restrict__ bq, const float* __restrict__ bk,
        const float* __restrict__ bv) {
    extern __shared__ char smem[];
    uint32_t sb = smem_u32(smem);
    int tid = threadIdx.x;
    int wid = tid >> 5, lane = tid & 31;
    int m0 = blockIdx.x * 128;
    int n0 = blockIdx.y * 64;
    int wr = wid & 3, wc = wid >> 2;

    float acc[3][2][4][4];
    #pragma unroll
    for (int w = 0; w < 3; w++)
        #pragma unroll
        for (int a = 0; a < 2; a++)
            #pragma unroll
            for (int b = 0; b < 4; b++)
                #pragma unroll
                for (int c = 0; c < 4; c++) acc[w][a][b][c] = 0.f;

    {
        uint32_t base = sb;
        for (int u = tid; u < 1024; u += 256) {
            int row = u >> 3, c = u & 7;
            uint32_t dst = (uint32_t)(((row << 3) | (c ^ (row & 7))) << 4);
            size_t go = (size_t)(m0 + row)*HID + c*8;
            cpa16(base + QAH + dst, g_Xhi + go);
            cpa16(base + QAL + dst, g_Xlo + go);
        }
        for (int u = tid; u < 1536; u += 256) {
            int w = u >> 9, r = (u >> 3) & 63, c = u & 7;
            uint32_t dst = (uint32_t)(((r << 3) | (c ^ (r & 7))) << 4);
            size_t go = (size_t)w*HID*HID + (size_t)(n0 + r)*HID + c*8;
            cpa16(base + QB0 + w*16384 + dst,        g_Wthi + go);
            cpa16(base + QB0 + w*16384 + 8192 + dst, g_Wtlo + go);
        }
        CP_COMMIT();
    }

    for (int ch = 0; ch < 8; ch++) {
        uint32_t cbase = sb + (uint32_t)(ch & 1)*QBUF;
        if (ch < 7) {
            uint32_t nbase = sb + (uint32_t)((ch+1) & 1)*QBUF;
            int k0 = (ch+1) * 64;
            for (int u = tid; u < 1024; u += 256) {
                int row = u >> 3, c = u & 7;
                uint32_t dst = (uint32_t)(((row << 3) | (c ^ (row & 7))) << 4);
                size_t go = (size_t)(m0 + row)*HID + k0 + c*8;
                cpa16(nbase + QAH + dst, g_Xhi + go);
                cpa16(nbase + QAL + dst, g_Xlo + go);
            }
            for (int u = tid; u < 1536; u += 256) {
                int w = u >> 9, r = (u >> 3) & 63, c = u & 7;
                uint32_t dst = (uint32_t)(((r << 3) | (c ^ (r & 7))) << 4);
                size_t go = (size_t)w*HID*HID + (size_t)(n0 + r)*HID + k0 + c*8;
                cpa16(nbase + QB0 + w*16384 + dst,        g_Wthi + go);
                cpa16(nbase + QB0 + w*16384 + 8192 + dst, g_Wtlo + go);
            }
            CP_COMMIT();
            CP_WAIT(1);
        } else {
            CP_WAIT(0);
        }
        __syncthreads();
        #pragma unroll
        for (int s = 0; s < 4; s++) {
            uint32_t ah[2][4], al[2][4];
            {
                int arow = wr*32 + (lane & 15);
                int ac   = s*2 + (lane >> 4);
                #pragma unroll
                for (int mt = 0; mt < 2; mt++) {
                    int r = arow + mt*16;
                    uint32_t off = (uint32_t)(((r << 3) | (ac ^ (r & 7))) << 4);
                    ldsm_x4(ah[mt], cbase + QAH + off);
                    ldsm_x4(al[mt], cbase + QAL + off);
                }
            }
            int brow = wc*32 + (lane & 7) + ((lane >> 4) << 3);
            int bc   = s*2 + ((lane >> 3) & 1);
            #pragma unroll
            for (int w = 0; w < 3; w++) {
                uint32_t bh[2][4], bl[2][4];
                #pragma unroll
                for (int bt = 0; bt < 2; bt++) {
                    int r = brow + bt*16;
                    uint32_t off = (uint32_t)(((r << 3) | (bc ^ (r & 7))) << 4);
                    ldsm_x4(bh[bt], cbase + QB0 + w*16384 + off);
                    ldsm_x4(bl[bt], cbase + QB0 + w*16384 + 8192 + off);
                }
                #pragma unroll
                for (int mt = 0; mt < 2; mt++)
                    #pragma unroll
                    for (int n8 = 0; n8 < 4; n8++) {
                        const uint32_t* B0 = &bh[n8 >> 1][(n8 & 1) * 2];
                        const uint32_t* L0 = &bl[n8 >> 1][(n8 & 1) * 2];
                        mma16816(acc[w][mt][n8], ah[mt], B0);
                        mma16816(acc[w][mt][n8], ah[mt], L0);
                        mma16816(acc[w][mt][n8], al[mt], B0);
                    }
            }
        }
        __syncthreads();
    }
    int rbase = m0 + wr*32 + (lane >> 2);
    int cbase2 = n0 + wc*32 + 2*(lane & 3);
    #pragma unroll
    for (int w = 0; w < 3; w++) {
        const float* bias = (w == 0) ? bq : (w == 1) ? bk : bv;
        __nv_bfloat16* outhi = (w == 0) ? g_Qhi : (w == 1) ? g_Khi : g_Vhi;
        __nv_bfloat16* outlo = (w == 0) ? g_Qlo : (w == 1) ? g_Klo : (__nv_bfloat16*)0;
        #pragma unroll
        for (int mt = 0; mt < 2; mt++) {
            #pragma unroll
            for (int n8 = 0; n8 < 4; n8++) {
                int col = cbase2 + n8*8;
                float b0 = bias[col], b1 = bias[col+1];
                #pragma unroll
                for (int half = 0; half < 2; half++) {
                    int r0 = rbase + mt*16 + half*8;
                    if (r0 >= NROWS) continue;
                    float v0 = acc[w][mt][n8][half*2+0] + b0;
                    float v1 = acc[w][mt][n8][half*2+1] + b1;
                    float h0 = __bfloat162float(__float2bfloat16(v0));
                    float h1 = __bfloat162float(__float2bfloat16(v1));
                    *(uint32_t*)(outhi + (size_t)r0*HID + col) = pkbf2(v0, v1);
                    if (outlo)
                        *(uint32_t*)(outlo + (size_t)r0*HID + col) = pkbf2(v0 - h0, v1 - h1);
                }
            }
        }
    }
}

// ---------------- flash attention: 2 kt-groups x 4 warps, Q in regs, db K/V ----------------
// smem: group g: 2 buffers of 24KB at g*49152; l-exchange 512B at 98304
#define AKVBUF 24576
#define AGRP   49152
#define ALX    98304
#define ATTN_SMEM 98816

__global__ void __launch_bounds__(256) k_attn_mma(const int* __restrict__ cell_ids,
                                                  const int* __restrict__ counts) {
    extern __shared__ char smem[];
    uint32_t sb = smem_u32(smem);
    int g = blockIdx.x, h = blockIdx.y;
    int tid = threadIdx.x, wid = tid >> 5, lane = tid & 31;
    int grp = wid >> 2, wr = wid & 3, ltid = tid & 127;
    int c = cell_ids[g];
    int nt = counts[c];
    int ks0 = g_cs[c];
    int arow = wr*16 + (lane & 15);

    // stage Q hi/lo into smem[0..16K), pull fragments to registers (both groups)
    uint32_t qah[4][4], qal[4][4];
    {
        for (int u = tid; u < 512; u += 256) {
            int row = u >> 3, ch = u & 7;
            uint32_t dst = (uint32_t)(((row << 3) | (ch ^ (row & 7))) << 4);
            size_t go = (size_t)(g*64 + row)*HID + h*64 + ch*8;
            *(uint4*)(smem + dst)        = *(const uint4*)(g_Qhi + go);
            *(uint4*)(smem + 8192 + dst) = *(const uint4*)(g_Qlo + go);
        }
        __syncthreads();
        #pragma unroll
        for (int s = 0; s < 4; s++) {
            int ac = s*2 + (lane >> 4);
            uint32_t aoff = (uint32_t)(((arow << 3) | (ac ^ (arow & 7))) << 4);
            ldsm_x4(qah[s], sb + aoff);
            ldsm_x4(qal[s], sb + 8192 + aoff);
        }
        __syncthreads();
    }

    int myn = (nt - grp + 1) >> 1;        // tiles for this group (kt = grp, grp+2, ...)
    uint32_t GB = sb + (uint32_t)grp*AGRP;

    // prologue prefetch: first tile of this group
    {
        int kg = ks0 + grp;
        for (int u = ltid; u < 512; u += 128) {
            int row = u >> 3, ch = u & 7;
            uint32_t dst = (uint32_t)(((row << 3) | (ch ^ (row & 7))) << 4);
            size_t go = (size_t)(kg*64 + row)*HID + h*64 + ch*8;
            cpa16(GB + dst,         g_Khi + go);
            cpa16(GB + 8192 + dst,  g_Klo + go);
            cpa16(GB + 16384 + dst, g_Vhi + go);
        }
        CP_COMMIT();
    }

    float oacc[8][4];
    #pragma unroll
    for (int t = 0; t < 8; t++)
        #pragma unroll
        for (int j = 0; j < 4; j++) oacc[t][j] = 0.f;
    float lA = 0.f, lB = 0.f;

    for (int i = 0; i < myn; i++) {
        uint32_t kb = GB + (uint32_t)(i & 1)*AKVBUF;
        if (i + 1 < myn) {
            uint32_t nb = GB + (uint32_t)((i+1) & 1)*AKVBUF;
            int kg = ks0 + grp + 2*(i+1);
            for (int u = ltid; u < 512; u += 128) {
                int row = u >> 3, ch = u & 7;
                uint32_t dst = (uint32_t)(((row << 3) | (ch ^ (row & 7))) << 4);
                size_t go = (size_t)(kg*64 + row)*HID + h*64 + ch*8;
                cpa16(nb + dst,         g_Khi + go);
                cpa16(nb + 8192 + dst,  g_Klo + go);
                cpa16(nb + 16384 + dst, g_Vhi + go);
            }
            CP_COMMIT();
            CP_WAIT(1);
        } else {
            CP_WAIT(0);
        }
        BAR_SYNC(grp + 1, 128);

        float sacc[8][4];
        #pragma unroll
        for (int t = 0; t < 8; t++)
            #pragma unroll
            for (int j = 0; j < 4; j++) sacc[t][j] = 0.f;
        #pragma unroll
        for (int s = 0; s < 4; s++) {
            #pragma unroll
            for (int bt = 0; bt < 4; bt++) {
                int brow = bt*16 + (lane & 7) + ((lane >> 4) << 3);
                int bc   = s*2 + ((lane >> 3) & 1);
                uint32_t boff = (uint32_t)(((brow << 3) | (bc ^ (brow & 7))) << 4);
                uint32_t bh[4], bl[4];
                ldsm_x4(bh, kb + boff);
                ldsm_x4(bl, kb + 8192 + boff);
                mma16816(sacc[bt*2],   qah[s], &bh[0]);
                mma16816(sacc[bt*2],   qah[s], &bl[0]);
                mma16816(sacc[bt*2],   qal[s], &bh[0]);
                mma16816(sacc[bt*2+1], qah[s], &bh[2]);
                mma16816(sacc[bt*2+1], qah[s], &bl[2]);
                mma16816(sacc[bt*2+1], qal[s], &bh[2]);
            }
        }
        float ltA = 0.f, ltB = 0.f;
        #pragma unroll
        for (int t = 0; t < 8; t++) {
            sacc[t][0] = __expf(sacc[t][0]*0.125f);
            sacc[t][1] = __expf(sacc[t][1]*0.125f);
            sacc[t][2] = __expf(sacc[t][2]*0.125f);
            sacc[t][3] = __expf(sacc[t][3]*0.125f);
            ltA += sacc[t][0] + sacc[t][1];
            ltB += sacc[t][2] + sacc[t][3];
        }
        ltA += __shfl_xor_sync(~0u, ltA, 1); ltA += __shfl_xor_sync(~0u, ltA, 2);
        ltB += __shfl_xor_sync(~0u, ltB, 1); ltB += __shfl_xor_sync(~0u, ltB, 2);
        lA += ltA; lB += ltB;
        #pragma unroll
        for (int t2 = 0; t2 < 4; t2++) {
            uint32_t pa[4];
            pa[0] = pkbf2(sacc[2*t2][0],   sacc[2*t2][1]);
            pa[1] = pkbf2(sacc[2*t2][2],   sacc[2*t2][3]);
            pa[2] = pkbf2(sacc[2*t2+1][0], sacc[2*t2+1][1]);
            pa[3] = pkbf2(sacc[2*t2+1][2], sacc[2*t2+1][3]);
            int lg = lane >> 3;
            int vrow = t2*16 + (lane & 7) + ((lg & 1) << 3);
            #pragma unroll
            for (int dblk = 0; dblk < 4; dblk++) {
                int vch = dblk*2 + (lg >> 1);
                uint32_t voff = (uint32_t)(((vrow << 3) | (vch ^ (vrow & 7))) << 4);
                uint32_t vb[4];
                ldsm_x4_t(vb, kb + 16384 + voff);
                mma16816(oacc[dblk*2],   pa, &vb[0]);
                mma16816(oacc[dblk*2+1], pa, &vb[2]);
            }
        }
        BAR_SYNC(grp + 1, 128);
    }

    // cross-group l exchange (rows rA/rB per thread, replicated x4 lanes)
    __syncthreads();
    int rA = wr*16 + (lane >> 2), rB = rA + 8;
    float* lx = (float*)(smem + ALX);
    if ((lane & 3) == 0) { lx[grp*64 + rA] = lA; lx[grp*64 + rB] = lB; }
    __syncthreads();
    float lAt = lA + lx[(1-grp)*64 + rA];
    float lBt = lB + lx[(1-grp)*64 + rB];

    float invA = 1.f / lAt, invB = 1.f / lBt;
    float invS = 1.f / (float)(nt * 64);
    #pragma unroll
    for (int t = 0; t < 8; t++) {
        float s0 = oacc[t][0]*invA + oacc[t][2]*invB;
        float s1 = oacc[t][1]*invA + oacc[t][3]*invB;
        #pragma unroll
        for (int off = 4; off < 32; off <<= 1) {
            s0 += __shfl_xor_sync(~0u, s0, off);
            s1 += __shfl_xor_sync(~0u, s1, off);
        }
        if (lane < 4) {
            int col = h*64 + 2*lane + t*8;
            atomicAdd(g_csum + c*HID + col,     s0 * invS);
            atomicAdd(g_csum + c*HID + col + 1, s1 * invS);
        }
    }
}

// ---------------- k-split batched vec-mat ----------------
template<int KDIM, int NCOL, int RELUIN, int SRC>
__global__ void __launch_bounds__(256) k_vm2(const float* __restrict__ W,
                                             const float* __restrict__ bias) {
    const float* vin  = (SRC == 0) ? g_csum  : (SRC == 1) ? g_meanh : g_h1;
    float*       vout = (SRC == 0) ? g_meanh : (SRC == 1) ? g_h1    : g_h2;
    int n0 = blockIdx.x * 64, kb = blockIdx.y * 128;
    int tid = threadIdx.x;
    __shared__ float sp[128][68];
    __shared__ float sw[16][68];
    for (int u = tid; u < 2048; u += 256) {
        int c = u >> 5, kq = (u & 31) * 4;
        float4 v = *(const float4*)(vin + c*KDIM + kb + kq);
        if (RELUIN) {
            v.x = fmaxf(v.x, 0.f); v.y = fmaxf(v.y, 0.f);
            v.z = fmaxf(v.z, 0.f); v.w = fmaxf(v.w, 0.f);
        }
        sp[kq+0][c] = v.x; sp[kq+1][c] = v.y;
        sp[kq+2][c] = v.z; sp[kq+3][c] = v.w;
    }
    u64 acc2[4][2];
    #pragma unroll
    for (int i = 0; i < 4; i++) { acc2[i][0] = 0ull; acc2[i][1] = 0ull; }
    int tb = (tid & 15) * 4;
    int th = (tid >> 4) * 4;
    int lr = tid >> 4, lc = (tid & 15) * 4;
    __syncthreads();
    for (int k0 = 0; k0 < 128; k0 += 16) {
        *(float4*)&sw[lr][lc] = *(const float4*)(W + (size_t)(kb + k0 + lr)*NCOL + n0 + lc);
        __syncthreads();
        #pragma unroll
        for (int kk = 0; kk < 16; kk++) {
            float4 a = *(float4*)&sp[k0+kk][tb];
            u64 b0 = *(u64*)&sw[kk][th];
            u64 b1 = *(u64*)&sw[kk][th+2];
            float av[4] = {a.x, a.y, a.z, a.w};
            #pragma unroll
            for (int i = 0; i < 4; i++) {
                u64 ad = dup2(av[i]);
                acc2[i][0] = ffma2(ad, b0, acc2[i][0]);
                acc2[i][1] = ffma2(ad, b1, acc2[i][1]);
            }
        }
        __syncthreads();
    }
    #pragma unroll
    for (int i = 0; i < 4; i++) {
        int c = tb + i;
        float2 f0 = up2(acc2[i][0]), f1 = up2(acc2[i][1]);
        float o[4] = {f0.x, f0.y, f1.x, f1.y};
        #pragma unroll
        for (int j = 0; j < 4; j++) {
            if (blockIdx.y == 0) o[j] += bias[n0 + th + j];
            atomicAdd(vout + (size_t)c*NCOL + n0 + th + j, o[j]);
        }
    }
}

// ---------------- layernorm ----------------
__global__ void k_ln(const float* __restrict__ lng, const float* __restrict__ lnb,
                     float* __restrict__ out) {
    int c = blockIdx.x, t = threadIdx.x;
    __shared__ float sh[34];
    float v0 = g_h2[c*HID + t], v1 = g_h2[c*HID + 256 + t];
    int lane = t & 31, w = t >> 5;
    float s = v0 + v1;
    #pragma unroll
    for (int off = 16; off; off >>= 1) s += __shfl_xor_sync(~0u, s, off);
    if (lane == 0) sh[w] = s;
    __syncthreads();
    if (w == 0) {
        float tot = (t < 8) ? sh[t] : 0.f;
        #pragma unroll
        for (int off = 4; off; off >>= 1) tot += __shfl_xor_sync(~0u, tot, off);
        if (t == 0) sh[32] = tot;
    }
    __syncthreads();
    float mu = sh[32] * (1.f/512.f);
    float d0 = v0 - mu, d1 = v1 - mu;
    float q = d0*d0 + d1*d1;
    #pragma unroll
    for (int off = 16; off; off >>= 1) q += __shfl_xor_sync(~0u, q, off);
    if (lane == 0) sh[w] = q;
    __syncthreads();
    if (w == 0) {
        float tot = (t < 8) ? sh[t] : 0.f;
        #pragma unroll
        for (int off = 4; off; off >>= 1) tot += __shfl_xor_sync(~0u, tot, off);
        if (t == 0) sh[33] = tot;
    }
    __syncthreads();
    float inv = rsqrtf(sh[33] * (1.f/512.f) + 1e-5f);
    float r0 = d0*inv*lng[t]     + lnb[t];
    float r1 = d1*inv*lng[256+t] + lnb[256+t];
    g_int[c*HID + t]       = r0;
    g_int[c*HID + 256 + t] = r1;
    out[64 + c*HID + t]       = r0;
    out[64 + c*HID + 256 + t] = r1;
}

// ---------------- per-cell affinity head (8 blocks/cell, fused sigmoid) ----------------
__global__ void __launch_bounds__(64) k_aff(const float* __restrict__ Aw1,
                                            const float* __restrict__ Ab1,
                                            const float* __restrict__ Aw2,
                                            const float* __restrict__ Ab2,
                                            float* __restrict__ out) {
    int c = blockIdx.x;
    int k = blockIdx.y * 64 + threadIdx.x;
    __shared__ float a[HID];
    __shared__ float red[2];
    for (int j = threadIdx.x; j < HID; j += 64) a[j] = g_int[c*HID + j];
    __syncthreads();
    float acc = Ab1[c*HID + k];
    const float* W = Aw1 + (size_t)c*HID*HID + k;
    #pragma unroll 8
    for (int j = 0; j < HID; j++) acc += a[j] * W[(size_t)j*HID];
    float part = fmaxf(acc, 0.f) * Aw2[c*HID + k];
    int lane = threadIdx.x & 31, w = threadIdx.x >> 5;
    #pragma unroll
    for (int off = 16; off; off >>= 1) part += __shfl_xor_sync(~0u, part, off);
    if (lane == 0) red[w] = part;
    __syncthreads();
    if (threadIdx.x == 0) {
        atomicAdd(&g_affacc[c], red[0] + red[1]);
        __threadfence();
        int done = atomicAdd(&g_affcnt[c], 1);
        if (done == 7) {
            float s = *((volatile float*)&g_affacc[c]);
            out[c] = 1.f / (1.f + expf(-(s + Ab2[c])));
        }
    }
}

extern "C" void kernel_launch(void* const* d_in, const int* in_sizes, int n_in,
                              void* d_out, int out_size) {
    const float* x       = (const float*)d_in[0];
    const int*   ei      = (const int*)  d_in[1];
    const float* gene_W  = (const float*)d_in[3];
    const float* gene_b  = (const float*)d_in[4];
    const int*   cell_ids= (const int*)  d_in[5];
    const int*   counts  = (const int*)  d_in[7];
    const float* Wq = (const float*)d_in[8],  *bq = (const float*)d_in[9];
    const float* Wk = (const float*)d_in[10], *bk = (const float*)d_in[11];
    const float* Wv = (const float*)d_in[12], *bv = (const float*)d_in[13];
    const float* Wo = (const float*)d_in[14], *bo = (const float*)d_in[15];
    const float* Wi1= (const float*)d_in[16], *bi1= (const float*)d_in[17];
    const float* Wi2= (const float*)d_in[18], *bi2= (const float*)d_in[19];
    const float* lng= (const float*)d_in[20], *lnb= (const float*)d_in[21];
    const float* Aw1= (const float*)d_in[22], *Ab1= (const float*)d_in[23];
    const float* Aw2= (const float*)d_in[24], *Ab2= (const float*)d_in[25];
    float* out = (float*)d_out;

    cudaFuncSetAttribute(k_attn_mma, cudaFuncAttributeMaxDynamicSharedMemorySize, ATTN_SMEM);
    cudaFuncSetAttribute(k_qkv_mma, cudaFuncAttributeMaxDynamicSharedMemorySize, QKV_SMEM);
    cudaFuncSetAttribute(k_gene_mma, cudaFuncAttributeMaxDynamicSharedMemorySize, GENE_SMEM);

    k_prep <<<1024, 256>>>(counts, Wq, Wk, Wv);
    k_edges<<<(NEDGES*32)/256, 256>>>(x, ei);
    k_pool <<<NB, 128>>>(x);
    k_gene_mma<<<dim3(NG, 8), 256, GENE_SMEM>>>(gene_W, gene_b);
    k_qkv_mma<<<dim3(MTILES, 8), 256, QKV_SMEM>>>(bq, bk, bv);
    k_attn_mma<<<dim3(NG, 8), 256, ATTN_SMEM>>>(cell_ids, counts);
    k_vm2<512,  512, 0, 0><<<dim3(8, 4),  256>>>(Wo,  bo);
    k_vm2<512, 1024, 0, 1><<<dim3(16, 4), 256>>>(Wi1, bi1);
    k_vm2<1024, 512, 1, 2><<<dim3(8, 8),  256>>>(Wi2, bi2);
    k_ln  <<<NC, 256>>>(lng, lnb, out);
    k_aff <<<dim3(NC, 8), 64>>>(Aw1, Ab1, Aw2, Ab2, out);
}

// round 16
// speedup vs baseline: 1.1187x; 1.1187x over previous
#include <cuda_runtime.h>
#include <cuda_bf16.h>
#include <math.h>
#include <cstdint>

#define NNODES 4096
#define FEAT   128
#define NEDGES 65536
#define NG     317
#define NB     64
#define NC     64
#define HID    512
#define DH     64
#define NROWS  (NG*NB)
#define FFD    1024
#define MTILES 159
#define PADROWS (MTILES*128)

typedef unsigned long long u64;

// ---------------- f32x2 helpers ----------------
__device__ __forceinline__ u64 dup2(float x) {
    u64 r; asm("mov.b64 %0,{%1,%1};" : "=l"(r) : "f"(x)); return r;
}
__device__ __forceinline__ u64 ffma2(u64 a, u64 b, u64 c) {
    u64 d; asm("fma.rn.f32x2 %0,%1,%2,%3;" : "=l"(d) : "l"(a), "l"(b), "l"(c)); return d;
}
__device__ __forceinline__ float2 up2(u64 v) {
    float2 f; asm("mov.b64 {%0,%1},%2;" : "=f"(f.x), "=f"(f.y) : "l"(v)); return f;
}

// ---------------- mma.sync / cp.async helpers ----------------
__device__ __forceinline__ uint32_t smem_u32(const void* p) {
    uint32_t a; asm("{ .reg .u64 t; cvta.to.shared.u64 t, %1; cvt.u32.u64 %0, t; }"
                    : "=r"(a) : "l"(p)); return a;
}
__device__ __forceinline__ void ldsm_x4(uint32_t* r, uint32_t addr) {
    asm volatile("ldmatrix.sync.aligned.m8n8.x4.shared.b16 {%0,%1,%2,%3}, [%4];"
        : "=r"(r[0]), "=r"(r[1]), "=r"(r[2]), "=r"(r[3]) : "r"(addr));
}
__device__ __forceinline__ void ldsm_x4_t(uint32_t* r, uint32_t addr) {
    asm volatile("ldmatrix.sync.aligned.m8n8.x4.trans.shared.b16 {%0,%1,%2,%3}, [%4];"
        : "=r"(r[0]), "=r"(r[1]), "=r"(r[2]), "=r"(r[3]) : "r"(addr));
}
__device__ __forceinline__ void mma16816(float* d, const uint32_t* a, const uint32_t* b) {
    asm volatile("mma.sync.aligned.m16n8k16.row.col.f32.bf16.bf16.f32 "
        "{%0,%1,%2,%3}, {%4,%5,%6,%7}, {%8,%9}, {%0,%1,%2,%3};"
        : "+f"(d[0]), "+f"(d[1]), "+f"(d[2]), "+f"(d[3])
        : "r"(a[0]), "r"(a[1]), "r"(a[2]), "r"(a[3]), "r"(b[0]), "r"(b[1]));
}
__device__ __forceinline__ uint32_t pkbf2(float lo, float hi) {
    uint32_t r; asm("cvt.rn.bf16x2.f32 %0, %1, %2;" : "=r"(r) : "f"(hi), "f"(lo)); return r;
}
__device__ __forceinline__ void cpa16(uint32_t dst, const void* src) {
    asm volatile("cp.async.ca.shared.global [%0], [%1], 16;" :: "r"(dst), "l"(src));
}
#define CP_COMMIT() asm volatile("cp.async.commit_group;" ::: "memory")
#define CP_WAIT(n)  asm volatile("cp.async.wait_group %0;" :: "n"(n) : "memory")
__device__ __forceinline__ void red4(float* p, float4 v) {
    asm volatile("red.global.add.v4.f32 [%0], {%1,%2,%3,%4};"
        :: "l"(p), "f"(v.x), "f"(v.y), "f"(v.z), "f"(v.w) : "memory");
}

// ---------------- scratch ----------------
__device__ float g_deg[NNODES];
__device__ float g_agg[NNODES*FEAT];
__device__ float g_csum[NC*HID];
__device__ float g_meanh[NC*HID];
__device__ float g_h1[NC*FFD];
__device__ float g_h2[NC*HID];
__device__ float g_int[NC*HID];
__device__ float g_affacc[NC];
__device__ int   g_affcnt[NC];
__device__ int   g_cs[NC+1];
__device__ __nv_bfloat16 g_ph[NB*FEAT];
__device__ __nv_bfloat16 g_pl[NB*FEAT];
__device__ __nv_bfloat16 g_Xhi[(size_t)PADROWS*HID];
__device__ __nv_bfloat16 g_Xlo[(size_t)PADROWS*HID];
__device__ __nv_bfloat16 g_Wthi[3*HID*HID];   // [w][n][k]
__device__ __nv_bfloat16 g_Wtlo[3*HID*HID];
__device__ __nv_bfloat16 g_Qhi[(size_t)NROWS*HID];
__device__ __nv_bfloat16 g_Qlo[(size_t)NROWS*HID];
__device__ __nv_bfloat16 g_Khi[(size_t)NROWS*HID];
__device__ __nv_bfloat16 g_Klo[(size_t)NROWS*HID];
__device__ __nv_bfloat16 g_Vhi[(size_t)NROWS*HID];

// ---------------- prep: cvtW (blocks 0..767) + init (768..1023) ----------------
__global__ void __launch_bounds__(256) k_prep(const int* __restrict__ counts,
                                              const float* __restrict__ Wq,
                                              const float* __restrict__ Wk,
                                              const float* __restrict__ Wv) {
    int bid = blockIdx.x;
    if (bid < 768) {
        __shared__ float tile[32][33];
        int w = bid / 256;
        int rem = bid % 256;
        int kb = (rem / 16) * 32, nb = (rem % 16) * 32;
        const float* W = (w == 0) ? Wq : (w == 1) ? Wk : Wv;
        int tx = threadIdx.x & 31, ty = threadIdx.x >> 5;
        #pragma unroll
        for (int i = 0; i < 4; i++)
            tile[ty + i*8][tx] = W[(size_t)(kb + ty + i*8)*HID + nb + tx];
        __syncthreads();
        #pragma unroll
        for (int i = 0; i < 4; i++) {
            int n = nb + ty + i*8, k = kb + tx;
            float v = tile[tx][ty + i*8];
            __nv_bfloat16 h = __float2bfloat16(v);
            size_t o = (size_t)w*HID*HID + (size_t)n*HID + k;
            g_Wthi[o] = h;
            g_Wtlo[o] = __float2bfloat16(v - __bfloat162float(h));
        }
    } else {
        int i = (bid - 768) * 256 + threadIdx.x;
        const int nt = 256*256;
        if (i < NNODES) g_deg[i] = 0.f;
        for (int j = i; j < NNODES*FEAT; j += nt) g_agg[j] = 0.f;
        if (i < NC*HID) { g_csum[i] = 0.f; g_meanh[i] = 0.f; g_h2[i] = 0.f; }
        for (int j = i; j < NC*FFD; j += nt) g_h1[j] = 0.f;
        if (i < NC) { g_affacc[i] = 0.f; g_affcnt[i] = 0; }
        for (int j = i; j < (PADROWS - NROWS) * HID; j += nt) {
            g_Xhi[(size_t)NROWS*HID + j] = __float2bfloat16(0.f);
            g_Xlo[(size_t)NROWS*HID + j] = __float2bfloat16(0.f);
        }
        if (i == 0) {
            int s = 0;
            for (int c = 0; c < NC; c++) { g_cs[c] = s; s += counts[c]; }
            g_cs[NC] = s;
        }
    }
}

// ---------------- edge aggregation ----------------
__global__ void k_edges(const float* __restrict__ x, const int* __restrict__ ei) {
    int t = blockIdx.x * blockDim.x + threadIdx.x;
    int e = t >> 5, lane = t & 31;
    if (e >= NEDGES) return;
    int s = ei[e], d = ei[NEDGES + e];
    float4 v = *(const float4*)(x + (size_t)s*FEAT + lane*4);
    red4(g_agg + (size_t)d*FEAT + lane*4, v);
    if (lane == 0) atomicAdd(g_deg + d, 1.f);
}

// ---------------- per-graph mean pool -> bf16 hi/lo ----------------
__global__ void k_pool(const float* __restrict__ x) {
    int g = blockIdx.x, f = threadIdx.x;
    float s = 0.f;
    for (int n = g*64; n < g*64 + 64; n++) {
        float inv = 1.f / fmaxf(g_deg[n], 1.f);
        s += x[(size_t)n*FEAT + f] + g_agg[(size_t)n*FEAT + f] * inv;
    }
    s *= (1.f/64.f);
    __nv_bfloat16 h = __float2bfloat16(s);
    g_ph[g*FEAT + f] = h;
    g_pl[g*FEAT + f] = __float2bfloat16(s - __bfloat162float(h));
}

// ---------------- per-gene GEMM via mma.sync bf16, n-block=64 ----------------
#define GAH 0
#define GAL 16384
#define GBH 32768
#define GBL 49152
#define GENE_SMEM 65536

__global__ void __launch_bounds__(256) k_gene_mma(const float* __restrict__ gW,
                                                  const float* __restrict__ gb) {
    extern __shared__ char smem[];
    uint32_t sb = smem_u32(smem);
    int tid = threadIdx.x, wid = tid >> 5, lane = tid & 31;
    int g = blockIdx.x, n0 = blockIdx.y * 64;
    int wr = wid & 3, wc = wid >> 2;

    for (int u = tid; u < 1024; u += 256) {
        int row = u >> 4, c = u & 15;
        uint32_t dst = (uint32_t)(((row << 4) | (c ^ (row & 7))) << 4);
        int go = row*FEAT + c*8;
        cpa16(sb + GAH + dst, g_ph + go);
        cpa16(sb + GAL + dst, g_pl + go);
    }
    CP_COMMIT();
    for (int u = tid; u < 1024; u += 256) {
        int row = u >> 3, c = u & 7;
        const float* src = gW + (size_t)g*FEAT*HID + (size_t)row*HID + n0 + c*8;
        float4 f0 = *(const float4*)src;
        float4 f1 = *(const float4*)(src + 4);
        float v[8] = {f0.x,f0.y,f0.z,f0.w,f1.x,f1.y,f1.z,f1.w};
        float hh[8];
        #pragma unroll
        for (int p = 0; p < 8; p++) hh[p] = __bfloat162float(__float2bfloat16(v[p]));
        uint4 hv, lv;
        hv.x = pkbf2(v[0],v[1]); hv.y = pkbf2(v[2],v[3]);
        hv.z = pkbf2(v[4],v[5]); hv.w = pkbf2(v[6],v[7]);
        lv.x = pkbf2(v[0]-hh[0],v[1]-hh[1]); lv.y = pkbf2(v[2]-hh[2],v[3]-hh[3]);
        lv.z = pkbf2(v[4]-hh[4],v[5]-hh[5]); lv.w = pkbf2(v[6]-hh[6],v[7]-hh[7]);
        uint32_t dst = (uint32_t)(((row << 3) | (c ^ (row & 7))) << 4);
        *(uint4*)(smem + GBH + dst) = hv;
        *(uint4*)(smem + GBL + dst) = lv;
    }
    CP_WAIT(0);
    __syncthreads();

    float acc[4][4];
    #pragma unroll
    for (int t = 0; t < 4; t++)
        #pragma unroll
        for (int j = 0; j < 4; j++) acc[t][j] = 0.f;

    #pragma unroll
    for (int s = 0; s < 8; s++) {
        int arow = wr*16 + (lane & 15);
        int ac   = s*2 + (lane >> 4);
        uint32_t aoff = (uint32_t)(((arow << 4) | (ac ^ (arow & 7))) << 4);
        uint32_t ah[4], al[4];
        ldsm_x4(ah, sb + GAH + aoff);
        ldsm_x4(al, sb + GAL + aoff);
        int grp = lane >> 3;
        int vrow = s*16 + (lane & 7) + ((grp & 1) << 3);
        #pragma unroll
        for (int dblk = 0; dblk < 2; dblk++) {
            int vch = wc*4 + dblk*2 + (grp >> 1);
            uint32_t voff = (uint32_t)(((vrow << 3) | (vch ^ (vrow & 7))) << 4);
            uint32_t vbh[4], vbl[4];
            ldsm_x4_t(vbh, sb + GBH + voff);
            ldsm_x4_t(vbl, sb + GBL + voff);
            mma16816(acc[dblk*2],   ah, &vbh[0]);
            mma16816(acc[dblk*2],   ah, &vbl[0]);
            mma16816(acc[dblk*2],   al, &vbh[0]);
            mma16816(acc[dblk*2+1], ah, &vbh[2]);
            mma16816(acc[dblk*2+1], ah, &vbl[2]);
            mma16816(acc[dblk*2+1], al, &vbh[2]);
        }
    }
    int row0 = wr*16 + (lane >> 2);
    int cb = n0 + wc*32 + 2*(lane & 3);
    #pragma unroll
    for (int n8 = 0; n8 < 4; n8++) {
        int col = cb + n8*8;
        float b0 = gb[(size_t)g*HID + col], b1 = gb[(size_t)g*HID + col + 1];
        #pragma unroll
        for (int half = 0; half < 2; half++) {
            int row = g*64 + row0 + half*8;
            float v0 = fmaxf(acc[n8][half*2+0] + b0, 0.f);
            float v1 = fmaxf(acc[n8][half*2+1] + b1, 0.f);
            float h0 = __bfloat162float(__float2bfloat16(v0));
            float h1 = __bfloat162float(__float2bfloat16(v1));
            *(uint32_t*)(g_Xhi + (size_t)row*HID + col) = pkbf2(v0, v1);
            *(uint32_t*)(g_Xlo + (size_t)row*HID + col) = pkbf2(v0 - h0, v1 - h1);
        }
    }
}

// ---------------- fused Q+K+V GEMM, compensated (hi/lo W), double-buffered ----------------
#define QBUF 81920
#define QAH 0
#define QAL 16384
#define QB0 32768
#define QKV_SMEM (2*QBUF)

__global__ void __launch_bounds__(256, 1) k_qkv_mma(
        const float* __restrict__ bq, const float* __restrict__ bk,
        const float* __restrict__ bv) {
    extern __shared__ char smem[];
    uint32_t sb = smem_u32(smem);
    int tid = threadIdx.x;
    int wid = tid >> 5, lane = tid & 31;
    int m0 = blockIdx.x * 128;
    int n0 = blockIdx.y * 64;
    int wr = wid & 3, wc = wid >> 2;

    float acc[3][2][4][4];
    #pragma unroll
    for (int w = 0; w < 3; w++)
        #pragma unroll
        for (int a = 0; a < 2; a++)
            #pragma unroll
            for (int b = 0; b < 4; b++)
                #pragma unroll
                for (int c = 0; c < 4; c++) acc[w][a][b][c] = 0.f;

    {
        uint32_t base = sb;
        for (int u = tid; u < 1024; u += 256) {
            int row = u >> 3, c = u & 7;
            uint32_t dst = (uint32_t)(((row << 3) | (c ^ (row & 7))) << 4);
            size_t go = (size_t)(m0 + row)*HID + c*8;
            cpa16(base + QAH + dst, g_Xhi + go);
            cpa16(base + QAL + dst, g_Xlo + go);
        }
        for (int u = tid; u < 1536; u += 256) {
            int w = u >> 9, r = (u >> 3) & 63, c = u & 7;
            uint32_t dst = (uint32_t)(((r << 3) | (c ^ (r & 7))) << 4);
            size_t go = (size_t)w*HID*HID + (size_t)(n0 + r)*HID + c*8;
            cpa16(base + QB0 + w*16384 + dst,        g_Wthi + go);
            cpa16(base + QB0 + w*16384 + 8192 + dst, g_Wtlo + go);
        }
        CP_COMMIT();
    }

    for (int ch = 0; ch < 8; ch++) {
        uint32_t cbase = sb + (uint32_t)(ch & 1)*QBUF;
        if (ch < 7) {
            uint32_t nbase = sb + (uint32_t)((ch+1) & 1)*QBUF;
            int k0 = (ch+1) * 64;
            for (int u = tid; u < 1024; u += 256) {
                int row = u >> 3, c = u & 7;
                uint32_t dst = (uint32_t)(((row << 3) | (c ^ (row & 7))) << 4);
                size_t go = (size_t)(m0 + row)*HID + k0 + c*8;
                cpa16(nbase + QAH + dst, g_Xhi + go);
                cpa16(nbase + QAL + dst, g_Xlo + go);
            }
            for (int u = tid; u < 1536; u += 256) {
                int w = u >> 9, r = (u >> 3) & 63, c = u & 7;
                uint32_t dst = (uint32_t)(((r << 3) | (c ^ (r & 7))) << 4);
                size_t go = (size_t)w*HID*HID + (size_t)(n0 + r)*HID + k0 + c*8;
                cpa16(nbase + QB0 + w*16384 + dst,        g_Wthi + go);
                cpa16(nbase + QB0 + w*16384 + 8192 + dst, g_Wtlo + go);
            }
            CP_COMMIT();
            CP_WAIT(1);
        } else {
            CP_WAIT(0);
        }
        __syncthreads();
        #pragma unroll
        for (int s = 0; s < 4; s++) {
            uint32_t ah[2][4], al[2][4];
            {
                int arow = wr*32 + (lane & 15);
                int ac   = s*2 + (lane >> 4);
                #pragma unroll
                for (int mt = 0; mt < 2; mt++) {
                    int r = arow + mt*16;
                    uint32_t off = (uint32_t)(((r << 3) | (ac ^ (r & 7))) << 4);
                    ldsm_x4(ah[mt], cbase + QAH + off);
                    ldsm_x4(al[mt], cbase + QAL + off);
                }
            }
            int brow = wc*32 + (lane & 7) + ((lane >> 4) << 3);
            int bc   = s*2 + ((lane >> 3) & 1);
            #pragma unroll
            for (int w = 0; w < 3; w++) {
                uint32_t bh[2][4], bl[2][4];
                #pragma unroll
                for (int bt = 0; bt < 2; bt++) {
                    int r = brow + bt*16;
                    uint32_t off = (uint32_t)(((r << 3) | (bc ^ (r & 7))) << 4);
                    ldsm_x4(bh[bt], cbase + QB0 + w*16384 + off);
                    ldsm_x4(bl[bt], cbase + QB0 + w*16384 + 8192 + off);
                }
                #pragma unroll
                for (int mt = 0; mt < 2; mt++)
                    #pragma unroll
                    for (int n8 = 0; n8 < 4; n8++) {
                        const uint32_t* B0 = &bh[n8 >> 1][(n8 & 1) * 2];
                        const uint32_t* L0 = &bl[n8 >> 1][(n8 & 1) * 2];
                        mma16816(acc[w][mt][n8], ah[mt], B0);
                        mma16816(acc[w][mt][n8], ah[mt], L0);
                        mma16816(acc[w][mt][n8], al[mt], B0);
                    }
            }
        }
        __syncthreads();
    }
    int rbase = m0 + wr*32 + (lane >> 2);
    int cbase2 = n0 + wc*32 + 2*(lane & 3);
    #pragma unroll
    for (int w = 0; w < 3; w++) {
        const float* bias = (w == 0) ? bq : (w == 1) ? bk : bv;
        __nv_bfloat16* outhi = (w == 0) ? g_Qhi : (w == 1) ? g_Khi : g_Vhi;
        __nv_bfloat16* outlo = (w == 0) ? g_Qlo : (w == 1) ? g_Klo : (__nv_bfloat16*)0;
        #pragma unroll
        for (int mt = 0; mt < 2; mt++) {
            #pragma unroll
            for (int n8 = 0; n8 < 4; n8++) {
                int col = cbase2 + n8*8;
                float b0 = bias[col], b1 = bias[col+1];
                #pragma unroll
                for (int half = 0; half < 2; half++) {
                    int r0 = rbase + mt*16 + half*8;
                    if (r0 >= NROWS) continue;
                    float v0 = acc[w][mt][n8][half*2+0] + b0;
                    float v1 = acc[w][mt][n8][half*2+1] + b1;
                    float h0 = __bfloat162float(__float2bfloat16(v0));
                    float h1 = __bfloat162float(__float2bfloat16(v1));
                    *(uint32_t*)(outhi + (size_t)r0*HID + col) = pkbf2(v0, v1);
                    if (outlo)
                        *(uint32_t*)(outlo + (size_t)r0*HID + col) = pkbf2(v0 - h0, v1 - h1);
                }
            }
        }
    }
}

// ---------------- flash attention: Q in regs, K-hi scores, no-max softmax, db K/V ----------------
// smem per buffer: KH 8K | VH 8K = 16KB; 2 buffers = 32KB total
#define AKVBUF 16384
#define ATTN_SMEM 32768

__global__ void __launch_bounds__(128) k_attn_mma(const int* __restrict__ cell_ids,
                                                  const int* __restrict__ counts) {
    extern __shared__ char smem[];
    uint32_t sb = smem_u32(smem);
    int g = blockIdx.x, h = blockIdx.y;
    int tid = threadIdx.x, wid = tid >> 5, lane = tid & 31;
    int c = cell_ids[g];
    int nt = counts[c];
    int ks0 = g_cs[c];
    int arow = wid*16 + (lane & 15);

    // stage Q hi/lo into the 32KB (overwritten later), pull fragments to registers
    uint32_t qah[4][4], qal[4][4];
    {
        for (int u = tid; u < 512; u += 128) {
            int row = u >> 3, ch = u & 7;
            uint32_t dst = (uint32_t)(((row << 3) | (ch ^ (row & 7))) << 4);
            size_t go = (size_t)(g*64 + row)*HID + h*64 + ch*8;
            *(uint4*)(smem + dst)        = *(const uint4*)(g_Qhi + go);
            *(uint4*)(smem + 8192 + dst) = *(const uint4*)(g_Qlo + go);
        }
        __syncthreads();
        #pragma unroll
        for (int s = 0; s < 4; s++) {
            int ac = s*2 + (lane >> 4);
            uint32_t aoff = (uint32_t)(((arow << 3) | (ac ^ (arow & 7))) << 4);
            ldsm_x4(qah[s], sb + aoff);
            ldsm_x4(qal[s], sb + 8192 + aoff);
        }
        __syncthreads();
    }
    // prologue K/V prefetch into buffer 0
    {
        for (int u = tid; u < 512; u += 128) {
            int row = u >> 3, ch = u & 7;
            uint32_t dst = (uint32_t)(((row << 3) | (ch ^ (row & 7))) << 4);
            size_t go = (size_t)(ks0*64 + row)*HID + h*64 + ch*8;
            cpa16(sb + dst,        g_Khi + go);
            cpa16(sb + 8192 + dst, g_Vhi + go);
        }
        CP_COMMIT();
    }

    float oacc[8][4];
    #pragma unroll
    for (int t = 0; t < 8; t++)
        #pragma unroll
        for (int j = 0; j < 4; j++) oacc[t][j] = 0.f;
    float lA = 0.f, lB = 0.f;

    for (int kt = 0; kt < nt; kt++) {
        uint32_t kb = sb + (uint32_t)(kt & 1)*AKVBUF;
        if (kt + 1 < nt) {
            uint32_t nb = sb + (uint32_t)((kt+1) & 1)*AKVBUF;
            int kg = ks0 + kt + 1;
            for (int u = tid; u < 512; u += 128) {
                int row = u >> 3, ch = u & 7;
                uint32_t dst = (uint32_t)(((row << 3) | (ch ^ (row & 7))) << 4);
                size_t go = (size_t)(kg*64 + row)*HID + h*64 + ch*8;
                cpa16(nb + dst,        g_Khi + go);
                cpa16(nb + 8192 + dst, g_Vhi + go);
            }
            CP_COMMIT();
            CP_WAIT(1);
        } else {
            CP_WAIT(0);
        }
        __syncthreads();

        float sacc[8][4];
        #pragma unroll
        for (int t = 0; t < 8; t++)
            #pragma unroll
            for (int j = 0; j < 4; j++) sacc[t][j] = 0.f;
        #pragma unroll
        for (int s = 0; s < 4; s++) {
            #pragma unroll
            for (int bt = 0; bt < 4; bt++) {
                int brow = bt*16 + (lane & 7) + ((lane >> 4) << 3);
                int bc   = s*2 + ((lane >> 3) & 1);
                uint32_t boff = (uint32_t)(((brow << 3) | (bc ^ (brow & 7))) << 4);
                uint32_t bh[4];
                ldsm_x4(bh, kb + boff);
                mma16816(sacc[bt*2],   qah[s], &bh[0]);
                mma16816(sacc[bt*2],   qal[s], &bh[0]);
                mma16816(sacc[bt*2+1], qah[s], &bh[2]);
                mma16816(sacc[bt*2+1], qal[s], &bh[2]);
            }
        }
        float ltA = 0.f, ltB = 0.f;
        #pragma unroll
        for (int t = 0; t < 8; t++) {
            sacc[t][0] = __expf(sacc[t][0]*0.125f);
            sacc[t][1] = __expf(sacc[t][1]*0.125f);
            sacc[t][2] = __expf(sacc[t][2]*0.125f);
            sacc[t][3] = __expf(sacc[t][3]*0.125f);
            ltA += sacc[t][0] + sacc[t][1];
            ltB += sacc[t][2] + sacc[t][3];
        }
        ltA += __shfl_xor_sync(~0u, ltA, 1); ltA += __shfl_xor_sync(~0u, ltA, 2);
        ltB += __shfl_xor_sync(~0u, ltB, 1); ltB += __shfl_xor_sync(~0u, ltB, 2);
        lA += ltA; lB += ltB;
        #pragma unroll
        for (int t2 = 0; t2 < 4; t2++) {
            uint32_t pa[4];
            pa[0] = pkbf2(sacc[2*t2][0],   sacc[2*t2][1]);
            pa[1] = pkbf2(sacc[2*t2][2],   sacc[2*t2][3]);
            pa[2] = pkbf2(sacc[2*t2+1][0], sacc[2*t2+1][1]);
            pa[3] = pkbf2(sacc[2*t2+1][2], sacc[2*t2+1][3]);
            int grp = lane >> 3;
            int vrow = t2*16 + (lane & 7) + ((grp & 1) << 3);
            #pragma unroll
            for (int dblk = 0; dblk < 4; dblk++) {
                int vch = dblk*2 + (grp >> 1);
                uint32_t voff = (uint32_t)(((vrow << 3) | (vch ^ (vrow & 7))) << 4);
                uint32_t vb[4];
                ldsm_x4_t(vb, kb + 8192 + voff);
                mma16816(oacc[dblk*2],   pa, &vb[0]);
                mma16816(oacc[dblk*2+1], pa, &vb[2]);
            }
        }
        __syncthreads();
    }
    float invA = 1.f / lA, invB = 1.f / lB;
    float invS = 1.f / (float)(nt * 64);
    #pragma unroll
    for (int t = 0; t < 8; t++) {
        float s0 = oacc[t][0]*invA + oacc[t][2]*invB;
        float s1 = oacc[t][1]*invA + oacc[t][3]*invB;
        #pragma unroll
        for (int off = 4; off < 32; off <<= 1) {
            s0 += __shfl_xor_sync(~0u, s0, off);
            s1 += __shfl_xor_sync(~0u, s1, off);
        }
        if (lane < 4) {
            int col = h*64 + 2*lane + t*8;
            atomicAdd(g_csum + c*HID + col,     s0 * invS);
            atomicAdd(g_csum + c*HID + col + 1, s1 * invS);
        }
    }
}

// ---------------- k-split batched vec-mat ----------------
template<int KDIM, int NCOL, int RELUIN, int SRC>
__global__ void __launch_bounds__(256) k_vm2(const float* __restrict__ W,
                                             const float* __restrict__ bias) {
    const float* vin  = (SRC == 0) ? g_csum  : (SRC == 1) ? g_meanh : g_h1;
    float*       vout = (SRC == 0) ? g_meanh : (SRC == 1) ? g_h1    : g_h2;
    int n0 = blockIdx.x * 64, kb = blockIdx.y * 128;
    int tid = threadIdx.x;
    __shared__ float sp[128][68];
    __shared__ float sw[16][68];
    for (int u = tid; u < 2048; u += 256) {
        int c = u >> 5, kq = (u & 31) * 4;
        float4 v = *(const float4*)(vin + c*KDIM + kb + kq);
        if (RELUIN) {
            v.x = fmaxf(v.x, 0.f); v.y = fmaxf(v.y, 0.f);
            v.z = fmaxf(v.z, 0.f); v.w = fmaxf(v.w, 0.f);
        }
        sp[kq+0][c] = v.x; sp[kq+1][c] = v.y;
        sp[kq+2][c] = v.z; sp[kq+3][c] = v.w;
    }
    u64 acc2[4][2];
    #pragma unroll
    for (int i = 0; i < 4; i++) { acc2[i][0] = 0ull; acc2[i][1] = 0ull; }
    int tb = (tid & 15) * 4;
    int th = (tid >> 4) * 4;
    int lr = tid >> 4, lc = (tid & 15) * 4;
    __syncthreads();
    for (int k0 = 0; k0 < 128; k0 += 16) {
        *(float4*)&sw[lr][lc] = *(const float4*)(W + (size_t)(kb + k0 + lr)*NCOL + n0 + lc);
        __syncthreads();
        #pragma unroll
        for (int kk = 0; kk < 16; kk++) {
            float4 a = *(float4*)&sp[k0+kk][tb];
            u64 b0 = *(u64*)&sw[kk][th];
            u64 b1 = *(u64*)&sw[kk][th+2];
            float av[4] = {a.x, a.y, a.z, a.w};
            #pragma unroll
            for (int i = 0; i < 4; i++) {
                u64 ad = dup2(av[i]);
                acc2[i][0] = ffma2(ad, b0, acc2[i][0]);
                acc2[i][1] = ffma2(ad, b1, acc2[i][1]);
            }
        }
        __syncthreads();
    }
    #pragma unroll
    for (int i = 0; i < 4; i++) {
        int c = tb + i;
        float2 f0 = up2(acc2[i][0]), f1 = up2(acc2[i][1]);
        float o[4] = {f0.x, f0.y, f1.x, f1.y};
        #pragma unroll
        for (int j = 0; j < 4; j++) {
            if (blockIdx.y == 0) o[j] += bias[n0 + th + j];
            atomicAdd(vout + (size_t)c*NCOL + n0 + th + j, o[j]);
        }
    }
}

// ---------------- layernorm ----------------
__global__ void k_ln(const float* __restrict__ lng, const float* __restrict__ lnb,
                     float* __restrict__ out) {
    int c = blockIdx.x, t = threadIdx.x;
    __shared__ float sh[34];
    float v0 = g_h2[c*HID + t], v1 = g_h2[c*HID + 256 + t];
    int lane = t & 31, w = t >> 5;
    float s = v0 + v1;
    #pragma unroll
    for (int off = 16; off; off >>= 1) s += __shfl_xor_sync(~0u, s, off);
    if (lane == 0) sh[w] = s;
    __syncthreads();
    if (w == 0) {
        float tot = (t < 8) ? sh[t] : 0.f;
        #pragma unroll
        for (int off = 4; off; off >>= 1) tot += __shfl_xor_sync(~0u, tot, off);
        if (t == 0) sh[32] = tot;
    }
    __syncthreads();
    float mu = sh[32] * (1.f/512.f);
    float d0 = v0 - mu, d1 = v1 - mu;
    float q = d0*d0 + d1*d1;
    #pragma unroll
    for (int off = 16; off; off >>= 1) q += __shfl_xor_sync(~0u, q, off);
    if (lane == 0) sh[w] = q;
    __syncthreads();
    if (w == 0) {
        float tot = (t < 8) ? sh[t] : 0.f;
        #pragma unroll
        for (int off = 4; off; off >>= 1) tot += __shfl_xor_sync(~0u, tot, off);
        if (t == 0) sh[33] = tot;
    }
    __syncthreads();
    float inv = rsqrtf(sh[33] * (1.f/512.f) + 1e-5f);
    float r0 = d0*inv*lng[t]     + lnb[t];
    float r1 = d1*inv*lng[256+t] + lnb[256+t];
    g_int[c*HID + t]       = r0;
    g_int[c*HID + 256 + t] = r1;
    out[64 + c*HID + t]       = r0;
    out[64 + c*HID + 256 + t] = r1;
}

// ---------------- per-cell affinity head (8 blocks/cell, fused sigmoid) ----------------
__global__ void __launch_bounds__(64) k_aff(const float* __restrict__ Aw1,
                                            const float* __restrict__ Ab1,
                                            const float* __restrict__ Aw2,
                                            const float* __restrict__ Ab2,
                                            float* __restrict__ out) {
    int c = blockIdx.x;
    int k = blockIdx.y * 64 + threadIdx.x;
    __shared__ float a[HID];
    __shared__ float red[2];
    for (int j = threadIdx.x; j < HID; j += 64) a[j] = g_int[c*HID + j];
    __syncthreads();
    float acc = Ab1[c*HID + k];
    const float* W = Aw1 + (size_t)c*HID*HID + k;
    #pragma unroll 8
    for (int j = 0; j < HID; j++) acc += a[j] * W[(size_t)j*HID];
    float part = fmaxf(acc, 0.f) * Aw2[c*HID + k];
    int lane = threadIdx.x & 31, w = threadIdx.x >> 5;
    #pragma unroll
    for (int off = 16; off; off >>= 1) part += __shfl_xor_sync(~0u, part, off);
    if (lane == 0) red[w] = part;
    __syncthreads();
    if (threadIdx.x == 0) {
        atomicAdd(&g_affacc[c], red[0] + red[1]);
        __threadfence();
        int done = atomicAdd(&g_affcnt[c], 1);
        if (done == 7) {
            float s = *((volatile float*)&g_affacc[c]);
            out[c] = 1.f / (1.f + expf(-(s + Ab2[c])));
        }
    }
}

extern "C" void kernel_launch(void* const* d_in, const int* in_sizes, int n_in,
                              void* d_out, int out_size) {
    const float* x       = (const float*)d_in[0];
    const int*   ei      = (const int*)  d_in[1];
    const float* gene_W  = (const float*)d_in[3];
    const float* gene_b  = (const float*)d_in[4];
    const int*   cell_ids= (const int*)  d_in[5];
    const int*   counts  = (const int*)  d_in[7];
    const float* Wq = (const float*)d_in[8],  *bq = (const float*)d_in[9];
    const float* Wk = (const float*)d_in[10], *bk = (const float*)d_in[11];
    const float* Wv = (const float*)d_in[12], *bv = (const float*)d_in[13];
    const float* Wo = (const float*)d_in[14], *bo = (const float*)d_in[15];
    const float* Wi1= (const float*)d_in[16], *bi1= (const float*)d_in[17];
    const float* Wi2= (const float*)d_in[18], *bi2= (const float*)d_in[19];
    const float* lng= (const float*)d_in[20], *lnb= (const float*)d_in[21];
    const float* Aw1= (const float*)d_in[22], *Ab1= (const float*)d_in[23];
    const float* Aw2= (const float*)d_in[24], *Ab2= (const float*)d_in[25];
    float* out = (float*)d_out;

    cudaFuncSetAttribute(k_attn_mma, cudaFuncAttributeMaxDynamicSharedMemorySize, ATTN_SMEM);
    cudaFuncSetAttribute(k_qkv_mma, cudaFuncAttributeMaxDynamicSharedMemorySize, QKV_SMEM);
    cudaFuncSetAttribute(k_gene_mma, cudaFuncAttributeMaxDynamicSharedMemorySize, GENE_SMEM);

    k_prep <<<1024, 256>>>(counts, Wq, Wk, Wv);
    k_edges<<<(NEDGES*32)/256, 256>>>(x, ei);
    k_pool <<<NB, 128>>>(x);
    k_gene_mma<<<dim3(NG, 8), 256, GENE_SMEM>>>(gene_W, gene_b);
    k_qkv_mma<<<dim3(MTILES, 8), 256, QKV_SMEM>>>(bq, bk, bv);
    k_attn_mma<<<dim3(NG, 8), 128, ATTN_SMEM>>>(cell_ids, counts);
    k_vm2<512,  512, 0, 0><<<dim3(8, 4),  256>>>(Wo,  bo);
    k_vm2<512, 1024, 0, 1><<<dim3(16, 4), 256>>>(Wi1, bi1);
    k_vm2<1024, 512, 1, 2><<<dim3(8, 8),  256>>>(Wi2, bi2);
    k_ln  <<<NC, 256>>>(lng, lnb, out);
    k_aff <<<dim3(NC, 8), 64>>>(Aw1, Ab1, Aw2, Ab2, out);
}

// round 17
// speedup vs baseline: 1.1693x; 1.0453x over previous
#include <cuda_runtime.h>
#include <cuda_bf16.h>
#include <math.h>
#include <cstdint>

#define NNODES 4096
#define FEAT   128
#define NEDGES 65536
#define NG     317
#define NB     64
#define NC     64
#define HID    512
#define DH     64
#define NROWS  (NG*NB)
#define FFD    1024
#define MTILES 159
#define PADROWS (MTILES*128)

typedef unsigned long long u64;

// ---------------- f32x2 helpers ----------------
__device__ __forceinline__ u64 dup2(float x) {
    u64 r; asm("mov.b64 %0,{%1,%1};" : "=l"(r) : "f"(x)); return r;
}
__device__ __forceinline__ u64 ffma2(u64 a, u64 b, u64 c) {
    u64 d; asm("fma.rn.f32x2 %0,%1,%2,%3;" : "=l"(d) : "l"(a), "l"(b), "l"(c)); return d;
}
__device__ __forceinline__ float2 up2(u64 v) {
    float2 f; asm("mov.b64 {%0,%1},%2;" : "=f"(f.x), "=f"(f.y) : "l"(v)); return f;
}

// ---------------- mma.sync / cp.async helpers ----------------
__device__ __forceinline__ uint32_t smem_u32(const void* p) {
    uint32_t a; asm("{ .reg .u64 t; cvta.to.shared.u64 t, %1; cvt.u32.u64 %0, t; }"
                    : "=r"(a) : "l"(p)); return a;
}
__device__ __forceinline__ void ldsm_x4(uint32_t* r, uint32_t addr) {
    asm volatile("ldmatrix.sync.aligned.m8n8.x4.shared.b16 {%0,%1,%2,%3}, [%4];"
        : "=r"(r[0]), "=r"(r[1]), "=r"(r[2]), "=r"(r[3]) : "r"(addr));
}
__device__ __forceinline__ void ldsm_x4_t(uint32_t* r, uint32_t addr) {
    asm volatile("ldmatrix.sync.aligned.m8n8.x4.trans.shared.b16 {%0,%1,%2,%3}, [%4];"
        : "=r"(r[0]), "=r"(r[1]), "=r"(r[2]), "=r"(r[3]) : "r"(addr));
}
__device__ __forceinline__ void mma16816(float* d, const uint32_t* a, const uint32_t* b) {
    asm volatile("mma.sync.aligned.m16n8k16.row.col.f32.bf16.bf16.f32 "
        "{%0,%1,%2,%3}, {%4,%5,%6,%7}, {%8,%9}, {%0,%1,%2,%3};"
        : "+f"(d[0]), "+f"(d[1]), "+f"(d[2]), "+f"(d[3])
        : "r"(a[0]), "r"(a[1]), "r"(a[2]), "r"(a[3]), "r"(b[0]), "r"(b[1]));
}
__device__ __forceinline__ uint32_t pkbf2(float lo, float hi) {
    uint32_t r; asm("cvt.rn.bf16x2.f32 %0, %1, %2;" : "=r"(r) : "f"(hi), "f"(lo)); return r;
}
__device__ __forceinline__ void cpa16(uint32_t dst, const void* src) {
    asm volatile("cp.async.ca.shared.global [%0], [%1], 16;" :: "r"(dst), "l"(src));
}
#define CP_COMMIT() asm volatile("cp.async.commit_group;" ::: "memory")
#define CP_WAIT(n)  asm volatile("cp.async.wait_group %0;" :: "n"(n) : "memory")
__device__ __forceinline__ void red4(float* p, float4 v) {
    asm volatile("red.global.add.v4.f32 [%0], {%1,%2,%3,%4};"
        :: "l"(p), "f"(v.x), "f"(v.y), "f"(v.z), "f"(v.w) : "memory");
}

// ---------------- scratch ----------------
__device__ float g_deg[NNODES];
__device__ float g_agg[NNODES*FEAT];
__device__ float g_csum[NC*HID];
__device__ float g_meanh[NC*HID];
__device__ float g_h1[NC*FFD];
__device__ float g_h2[NC*HID];
__device__ float g_int[NC*HID];
__device__ float g_affacc[NC];
__device__ int   g_affcnt[NC];
__device__ int   g_cs[NC+1];
__device__ __nv_bfloat16 g_ph[NB*FEAT];
__device__ __nv_bfloat16 g_pl[NB*FEAT];
__device__ __nv_bfloat16 g_Xhi[(size_t)PADROWS*HID];
__device__ __nv_bfloat16 g_Xlo[(size_t)PADROWS*HID];
__device__ __nv_bfloat16 g_Wthi[3*HID*HID];   // [w][n][k]
__device__ __nv_bfloat16 g_Wtlo[3*HID*HID];
__device__ __nv_bfloat16 g_Qhi[(size_t)NROWS*HID];
__device__ __nv_bfloat16 g_Khi[(size_t)NROWS*HID];
__device__ __nv_bfloat16 g_Vhi[(size_t)NROWS*HID];

// ---------------- prep: cvtW (blocks 0..767) + init (768..1023) ----------------
__global__ void __launch_bounds__(256) k_prep(const int* __restrict__ counts,
                                              const float* __restrict__ Wq,
                                              const float* __restrict__ Wk,
                                              const float* __restrict__ Wv) {
    int bid = blockIdx.x;
    if (bid < 768) {
        __shared__ float tile[32][33];
        int w = bid / 256;
        int rem = bid % 256;
        int kb = (rem / 16) * 32, nb = (rem % 16) * 32;
        const float* W = (w == 0) ? Wq : (w == 1) ? Wk : Wv;
        int tx = threadIdx.x & 31, ty = threadIdx.x >> 5;
        #pragma unroll
        for (int i = 0; i < 4; i++)
            tile[ty + i*8][tx] = W[(size_t)(kb + ty + i*8)*HID + nb + tx];
        __syncthreads();
        #pragma unroll
        for (int i = 0; i < 4; i++) {
            int n = nb + ty + i*8, k = kb + tx;
            float v = tile[tx][ty + i*8];
            __nv_bfloat16 h = __float2bfloat16(v);
            size_t o = (size_t)w*HID*HID + (size_t)n*HID + k;
            g_Wthi[o] = h;
            g_Wtlo[o] = __float2bfloat16(v - __bfloat162float(h));
        }
    } else {
        int i = (bid - 768) * 256 + threadIdx.x;
        const int nt = 256*256;
        if (i < NNODES) g_deg[i] = 0.f;
        for (int j = i; j < NNODES*FEAT; j += nt) g_agg[j] = 0.f;
        if (i < NC*HID) { g_csum[i] = 0.f; g_meanh[i] = 0.f; g_h2[i] = 0.f; }
        for (int j = i; j < NC*FFD; j += nt) g_h1[j] = 0.f;
        if (i < NC) { g_affacc[i] = 0.f; g_affcnt[i] = 0; }
        for (int j = i; j < (PADROWS - NROWS) * HID; j += nt) {
            g_Xhi[(size_t)NROWS*HID + j] = __float2bfloat16(0.f);
            g_Xlo[(size_t)NROWS*HID + j] = __float2bfloat16(0.f);
        }
        if (i == 0) {
            int s = 0;
            for (int c = 0; c < NC; c++) { g_cs[c] = s; s += counts[c]; }
            g_cs[NC] = s;
        }
    }
}

// ---------------- edge aggregation ----------------
__global__ void k_edges(const float* __restrict__ x, const int* __restrict__ ei) {
    int t = blockIdx.x * blockDim.x + threadIdx.x;
    int e = t >> 5, lane = t & 31;
    if (e >= NEDGES) return;
    int s = ei[e], d = ei[NEDGES + e];
    float4 v = *(const float4*)(x + (size_t)s*FEAT + lane*4);
    red4(g_agg + (size_t)d*FEAT + lane*4, v);
    if (lane == 0) atomicAdd(g_deg + d, 1.f);
}

// ---------------- per-graph mean pool -> bf16 hi/lo ----------------
__global__ void k_pool(const float* __restrict__ x) {
    int g = blockIdx.x, f = threadIdx.x;
    float s = 0.f;
    for (int n = g*64; n < g*64 + 64; n++) {
        float inv = 1.f / fmaxf(g_deg[n], 1.f);
        s += x[(size_t)n*FEAT + f] + g_agg[(size_t)n*FEAT + f] * inv;
    }
    s *= (1.f/64.f);
    __nv_bfloat16 h = __float2bfloat16(s);
    g_ph[g*FEAT + f] = h;
    g_pl[g*FEAT + f] = __float2bfloat16(s - __bfloat162float(h));
}

// ---------------- per-gene GEMM via mma.sync bf16, n-block=64 ----------------
#define GAH 0
#define GAL 16384
#define GBH 32768
#define GBL 49152
#define GENE_SMEM 65536

__global__ void __launch_bounds__(256) k_gene_mma(const float* __restrict__ gW,
                                                  const float* __restrict__ gb) {
    extern __shared__ char smem[];
    uint32_t sb = smem_u32(smem);
    int tid = threadIdx.x, wid = tid >> 5, lane = tid & 31;
    int g = blockIdx.x, n0 = blockIdx.y * 64;
    int wr = wid & 3, wc = wid >> 2;

    for (int u = tid; u < 1024; u += 256) {
        int row = u >> 4, c = u & 15;
        uint32_t dst = (uint32_t)(((row << 4) | (c ^ (row & 7))) << 4);
        int go = row*FEAT + c*8;
        cpa16(sb + GAH + dst, g_ph + go);
        cpa16(sb + GAL + dst, g_pl + go);
    }
    CP_COMMIT();
    for (int u = tid; u < 1024; u += 256) {
        int row = u >> 3, c = u & 7;
        const float* src = gW + (size_t)g*FEAT*HID + (size_t)row*HID + n0 + c*8;
        float4 f0 = *(const float4*)src;
        float4 f1 = *(const float4*)(src + 4);
        float v[8] = {f0.x,f0.y,f0.z,f0.w,f1.x,f1.y,f1.z,f1.w};
        float hh[8];
        #pragma unroll
        for (int p = 0; p < 8; p++) hh[p] = __bfloat162float(__float2bfloat16(v[p]));
        uint4 hv, lv;
        hv.x = pkbf2(v[0],v[1]); hv.y = pkbf2(v[2],v[3]);
        hv.z = pkbf2(v[4],v[5]); hv.w = pkbf2(v[6],v[7]);
        lv.x = pkbf2(v[0]-hh[0],v[1]-hh[1]); lv.y = pkbf2(v[2]-hh[2],v[3]-hh[3]);
        lv.z = pkbf2(v[4]-hh[4],v[5]-hh[5]); lv.w = pkbf2(v[6]-hh[6],v[7]-hh[7]);
        uint32_t dst = (uint32_t)(((row << 3) | (c ^ (row & 7))) << 4);
        *(uint4*)(smem + GBH + dst) = hv;
        *(uint4*)(smem + GBL + dst) = lv;
    }
    CP_WAIT(0);
    __syncthreads();

    float acc[4][4];
    #pragma unroll
    for (int t = 0; t < 4; t++)
        #pragma unroll
        for (int j = 0; j < 4; j++) acc[t][j] = 0.f;

    #pragma unroll
    for (int s = 0; s < 8; s++) {
        int arow = wr*16 + (lane & 15);
        int ac   = s*2 + (lane >> 4);
        uint32_t aoff = (uint32_t)(((arow << 4) | (ac ^ (arow & 7))) << 4);
        uint32_t ah[4], al[4];
        ldsm_x4(ah, sb + GAH + aoff);
        ldsm_x4(al, sb + GAL + aoff);
        int grp = lane >> 3;
        int vrow = s*16 + (lane & 7) + ((grp & 1) << 3);
        #pragma unroll
        for (int dblk = 0; dblk < 2; dblk++) {
            int vch = wc*4 + dblk*2 + (grp >> 1);
            uint32_t voff = (uint32_t)(((vrow << 3) | (vch ^ (vrow & 7))) << 4);
            uint32_t vbh[4], vbl[4];
            ldsm_x4_t(vbh, sb + GBH + voff);
            ldsm_x4_t(vbl, sb + GBL + voff);
            mma16816(acc[dblk*2],   ah, &vbh[0]);
            mma16816(acc[dblk*2],   ah, &vbl[0]);
            mma16816(acc[dblk*2],   al, &vbh[0]);
            mma16816(acc[dblk*2+1], ah, &vbh[2]);
            mma16816(acc[dblk*2+1], ah, &vbl[2]);
            mma16816(acc[dblk*2+1], al, &vbh[2]);
        }
    }
    int row0 = wr*16 + (lane >> 2);
    int cb = n0 + wc*32 + 2*(lane & 3);
    #pragma unroll
    for (int n8 = 0; n8 < 4; n8++) {
        int col = cb + n8*8;
        float b0 = gb[(size_t)g*HID + col], b1 = gb[(size_t)g*HID + col + 1];
        #pragma unroll
        for (int half = 0; half < 2; half++) {
            int row = g*64 + row0 + half*8;
            float v0 = fmaxf(acc[n8][half*2+0] + b0, 0.f);
            float v1 = fmaxf(acc[n8][half*2+1] + b1, 0.f);
            float h0 = __bfloat162float(__float2bfloat16(v0));
            float h1 = __bfloat162float(__float2bfloat16(v1));
            *(uint32_t*)(g_Xhi + (size_t)row*HID + col) = pkbf2(v0, v1);
            *(uint32_t*)(g_Xlo + (size_t)row*HID + col) = pkbf2(v0 - h0, v1 - h1);
        }
    }
}

// ---------------- fused Q+K+V GEMM, compensated (hi/lo W), double-buffered ----------------
#define QBUF 81920
#define QAH 0
#define QAL 16384
#define QB0 32768
#define QKV_SMEM (2*QBUF)

__global__ void __launch_bounds__(256, 1) k_qkv_mma(
        const float* __restrict__ bq, const float* __restrict__ bk,
        const float* __restrict__ bv) {
    extern __shared__ char smem[];
    uint32_t sb = smem_u32(smem);
    int tid = threadIdx.x;
    int wid = tid >> 5, lane = tid & 31;
    int m0 = blockIdx.x * 128;
    int n0 = blockIdx.y * 64;
    int wr = wid & 3, wc = wid >> 2;

    float acc[3][2][4][4];
    #pragma unroll
    for (int w = 0; w < 3; w++)
        #pragma unroll
        for (int a = 0; a < 2; a++)
            #pragma unroll
            for (int b = 0; b < 4; b++)
                #pragma unroll
                for (int c = 0; c < 4; c++) acc[w][a][b][c] = 0.f;

    {
        uint32_t base = sb;
        for (int u = tid; u < 1024; u += 256) {
            int row = u >> 3, c = u & 7;
            uint32_t dst = (uint32_t)(((row << 3) | (c ^ (row & 7))) << 4);
            size_t go = (size_t)(m0 + row)*HID + c*8;
            cpa16(base + QAH + dst, g_Xhi + go);
            cpa16(base + QAL + dst, g_Xlo + go);
        }
        for (int u = tid; u < 1536; u += 256) {
            int w = u >> 9, r = (u >> 3) & 63, c = u & 7;
            uint32_t dst = (uint32_t)(((r << 3) | (c ^ (r & 7))) << 4);
            size_t go = (size_t)w*HID*HID + (size_t)(n0 + r)*HID + c*8;
            cpa16(base + QB0 + w*16384 + dst,        g_Wthi + go);
            cpa16(base + QB0 + w*16384 + 8192 + dst, g_Wtlo + go);
        }
        CP_COMMIT();
    }

    for (int ch = 0; ch < 8; ch++) {
        uint32_t cbase = sb + (uint32_t)(ch & 1)*QBUF;
        if (ch < 7) {
            uint32_t nbase = sb + (uint32_t)((ch+1) & 1)*QBUF;
            int k0 = (ch+1) * 64;
            for (int u = tid; u < 1024; u += 256) {
                int row = u >> 3, c = u & 7;
                uint32_t dst = (uint32_t)(((row << 3) | (c ^ (row & 7))) << 4);
                size_t go = (size_t)(m0 + row)*HID + k0 + c*8;
                cpa16(nbase + QAH + dst, g_Xhi + go);
                cpa16(nbase + QAL + dst, g_Xlo + go);
            }
            for (int u = tid; u < 1536; u += 256) {
                int w = u >> 9, r = (u >> 3) & 63, c = u & 7;
                uint32_t dst = (uint32_t)(((r << 3) | (c ^ (r & 7))) << 4);
                size_t go = (size_t)w*HID*HID + (size_t)(n0 + r)*HID + k0 + c*8;
                cpa16(nbase + QB0 + w*16384 + dst,        g_Wthi + go);
                cpa16(nbase + QB0 + w*16384 + 8192 + dst, g_Wtlo + go);
            }
            CP_COMMIT();
            CP_WAIT(1);
        } else {
            CP_WAIT(0);
        }
        __syncthreads();
        #pragma unroll
        for (int s = 0; s < 4; s++) {
            uint32_t ah[2][4], al[2][4];
            {
                int arow = wr*32 + (lane & 15);
                int ac   = s*2 + (lane >> 4);
                #pragma unroll
                for (int mt = 0; mt < 2; mt++) {
                    int r = arow + mt*16;
                    uint32_t off = (uint32_t)(((r << 3) | (ac ^ (r & 7))) << 4);
                    ldsm_x4(ah[mt], cbase + QAH + off);
                    ldsm_x4(al[mt], cbase + QAL + off);
                }
            }
            int brow = wc*32 + (lane & 7) + ((lane >> 4) << 3);
            int bc   = s*2 + ((lane >> 3) & 1);
            #pragma unroll
            for (int w = 0; w < 3; w++) {
                uint32_t bh[2][4], bl[2][4];
                #pragma unroll
                for (int bt = 0; bt < 2; bt++) {
                    int r = brow + bt*16;
                    uint32_t off = (uint32_t)(((r << 3) | (bc ^ (r & 7))) << 4);
                    ldsm_x4(bh[bt], cbase + QB0 + w*16384 + off);
                    ldsm_x4(bl[bt], cbase + QB0 + w*16384 + 8192 + off);
                }
                #pragma unroll
                for (int mt = 0; mt < 2; mt++)
                    #pragma unroll
                    for (int n8 = 0; n8 < 4; n8++) {
                        const uint32_t* B0 = &bh[n8 >> 1][(n8 & 1) * 2];
                        const uint32_t* L0 = &bl[n8 >> 1][(n8 & 1) * 2];
                        mma16816(acc[w][mt][n8], ah[mt], B0);
                        mma16816(acc[w][mt][n8], ah[mt], L0);
                        mma16816(acc[w][mt][n8], al[mt], B0);
                    }
            }
        }
        __syncthreads();
    }
    int rbase = m0 + wr*32 + (lane >> 2);
    int cbase2 = n0 + wc*32 + 2*(lane & 3);
    #pragma unroll
    for (int w = 0; w < 3; w++) {
        const float* bias = (w == 0) ? bq : (w == 1) ? bk : bv;
        __nv_bfloat16* outhi = (w == 0) ? g_Qhi : (w == 1) ? g_Khi : g_Vhi;
        #pragma unroll
        for (int mt = 0; mt < 2; mt++) {
            #pragma unroll
            for (int n8 = 0; n8 < 4; n8++) {
                int col = cbase2 + n8*8;
                float b0 = bias[col], b1 = bias[col+1];
                #pragma unroll
                for (int half = 0; half < 2; half++) {
                    int r0 = rbase + mt*16 + half*8;
                    if (r0 >= NROWS) continue;
                    float v0 = acc[w][mt][n8][half*2+0] + b0;
                    float v1 = acc[w][mt][n8][half*2+1] + b1;
                    *(uint32_t*)(outhi + (size_t)r0*HID + col) = pkbf2(v0, v1);
                }
            }
        }
    }
}

// ---------------- flash attention: Q-hi in regs, bf16 scores, no-max softmax, db K/V ----------------
// smem per buffer: KH 8K | VH 8K = 16KB; 2 buffers = 32KB total
#define AKVBUF 16384
#define ATTN_SMEM 32768

__global__ void __launch_bounds__(128) k_attn_mma(const int* __restrict__ cell_ids,
                                                  const int* __restrict__ counts) {
    extern __shared__ char smem[];
    uint32_t sb = smem_u32(smem);
    int g = blockIdx.x, h = blockIdx.y;
    int tid = threadIdx.x, wid = tid >> 5, lane = tid & 31;
    int c = cell_ids[g];
    int nt = counts[c];
    int ks0 = g_cs[c];
    int arow = wid*16 + (lane & 15);

    // stage Q hi into smem (overwritten later), pull fragments to registers
    uint32_t qah[4][4];
    {
        for (int u = tid; u < 512; u += 128) {
            int row = u >> 3, ch = u & 7;
            uint32_t dst = (uint32_t)(((row << 3) | (ch ^ (row & 7))) << 4);
            size_t go = (size_t)(g*64 + row)*HID + h*64 + ch*8;
            *(uint4*)(smem + dst) = *(const uint4*)(g_Qhi + go);
        }
        __syncthreads();
        #pragma unroll
        for (int s = 0; s < 4; s++) {
            int ac = s*2 + (lane >> 4);
            uint32_t aoff = (uint32_t)(((arow << 3) | (ac ^ (arow & 7))) << 4);
            ldsm_x4(qah[s], sb + aoff);
        }
        __syncthreads();
    }
    // prologue K/V prefetch into buffer 0
    {
        for (int u = tid; u < 512; u += 128) {
            int row = u >> 3, ch = u & 7;
            uint32_t dst = (uint32_t)(((row << 3) | (ch ^ (row & 7))) << 4);
            size_t go = (size_t)(ks0*64 + row)*HID + h*64 + ch*8;
            cpa16(sb + dst,        g_Khi + go);
            cpa16(sb + 8192 + dst, g_Vhi + go);
        }
        CP_COMMIT();
    }

    float oacc[8][4];
    #pragma unroll
    for (int t = 0; t < 8; t++)
        #pragma unroll
        for (int j = 0; j < 4; j++) oacc[t][j] = 0.f;
    float lA = 0.f, lB = 0.f;

    for (int kt = 0; kt < nt; kt++) {
        uint32_t kb = sb + (uint32_t)(kt & 1)*AKVBUF;
        if (kt + 1 < nt) {
            uint32_t nb = sb + (uint32_t)((kt+1) & 1)*AKVBUF;
            int kg = ks0 + kt + 1;
            for (int u = tid; u < 512; u += 128) {
                int row = u >> 3, ch = u & 7;
                uint32_t dst = (uint32_t)(((row << 3) | (ch ^ (row & 7))) << 4);
                size_t go = (size_t)(kg*64 + row)*HID + h*64 + ch*8;
                cpa16(nb + dst,        g_Khi + go);
                cpa16(nb + 8192 + dst, g_Vhi + go);
            }
            CP_COMMIT();
            CP_WAIT(1);
        } else {
            CP_WAIT(0);
        }
        __syncthreads();

        float sacc[8][4];
        #pragma unroll
        for (int t = 0; t < 8; t++)
            #pragma unroll
            for (int j = 0; j < 4; j++) sacc[t][j] = 0.f;
        #pragma unroll
        for (int s = 0; s < 4; s++) {
            #pragma unroll
            for (int bt = 0; bt < 4; bt++) {
                int brow = bt*16 + (lane & 7) + ((lane >> 4) << 3);
                int bc   = s*2 + ((lane >> 3) & 1);
                uint32_t boff = (uint32_t)(((brow << 3) | (bc ^ (brow & 7))) << 4);
                uint32_t bh[4];
                ldsm_x4(bh, kb + boff);
                mma16816(sacc[bt*2],   qah[s], &bh[0]);
                mma16816(sacc[bt*2+1], qah[s], &bh[2]);
            }
        }
        float ltA = 0.f, ltB = 0.f;
        #pragma unroll
        for (int t = 0; t < 8; t++) {
            sacc[t][0] = __expf(sacc[t][0]*0.125f);
            sacc[t][1] = __expf(sacc[t][1]*0.125f);
            sacc[t][2] = __expf(sacc[t][2]*0.125f);
            sacc[t][3] = __expf(sacc[t][3]*0.125f);
            ltA += sacc[t][0] + sacc[t][1];
            ltB += sacc[t][2] + sacc[t][3];
        }
        ltA += __shfl_xor_sync(~0u, ltA, 1); ltA += __shfl_xor_sync(~0u, ltA, 2);
        ltB += __shfl_xor_sync(~0u, ltB, 1); ltB += __shfl_xor_sync(~0u, ltB, 2);
        lA += ltA; lB += ltB;
        #pragma unroll
        for (int t2 = 0; t2 < 4; t2++) {
            uint32_t pa[4];
            pa[0] = pkbf2(sacc[2*t2][0],   sacc[2*t2][1]);
            pa[1] = pkbf2(sacc[2*t2][2],   sacc[2*t2][3]);
            pa[2] = pkbf2(sacc[2*t2+1][0], sacc[2*t2+1][1]);
            pa[3] = pkbf2(sacc[2*t2+1][2], sacc[2*t2+1][3]);
            int grp = lane >> 3;
            int vrow = t2*16 + (lane & 7) + ((grp & 1) << 3);
            #pragma unroll
            for (int dblk = 0; dblk < 4; dblk++) {
                int vch = dblk*2 + (grp >> 1);
                uint32_t voff = (uint32_t)(((vrow << 3) | (vch ^ (vrow & 7))) << 4);
                uint32_t vb[4];
                ldsm_x4_t(vb, kb + 8192 + voff);
                mma16816(oacc[dblk*2],   pa, &vb[0]);
                mma16816(oacc[dblk*2+1], pa, &vb[2]);
            }
        }
        __syncthreads();
    }
    float invA = 1.f / lA, invB = 1.f / lB;
    float invS = 1.f / (float)(nt * 64);
    #pragma unroll
    for (int t = 0; t < 8; t++) {
        float s0 = oacc[t][0]*invA + oacc[t][2]*invB;
        float s1 = oacc[t][1]*invA + oacc[t][3]*invB;
        #pragma unroll
        for (int off = 4; off < 32; off <<= 1) {
            s0 += __shfl_xor_sync(~0u, s0, off);
            s1 += __shfl_xor_sync(~0u, s1, off);
        }
        if (lane < 4) {
            int col = h*64 + 2*lane + t*8;
            atomicAdd(g_csum + c*HID + col,     s0 * invS);
            atomicAdd(g_csum + c*HID + col + 1, s1 * invS);
        }
    }
}

// ---------------- k-split batched vec-mat ----------------
template<int KDIM, int NCOL, int RELUIN, int SRC>
__global__ void __launch_bounds__(256) k_vm2(const float* __restrict__ W,
                                             const float* __restrict__ bias) {
    const float* vin  = (SRC == 0) ? g_csum  : (SRC == 1) ? g_meanh : g_h1;
    float*       vout = (SRC == 0) ? g_meanh : (SRC == 1) ? g_h1    : g_h2;
    int n0 = blockIdx.x * 64, kb = blockIdx.y * 128;
    int tid = threadIdx.x;
    __shared__ float sp[128][68];
    __shared__ float sw[16][68];
    for (int u = tid; u < 2048; u += 256) {
        int c = u >> 5, kq = (u & 31) * 4;
        float4 v = *(const float4*)(vin + c*KDIM + kb + kq);
        if (RELUIN) {
            v.x = fmaxf(v.x, 0.f); v.y = fmaxf(v.y, 0.f);
            v.z = fmaxf(v.z, 0.f); v.w = fmaxf(v.w, 0.f);
        }
        sp[kq+0][c] = v.x; sp[kq+1][c] = v.y;
        sp[kq+2][c] = v.z; sp[kq+3][c] = v.w;
    }
    u64 acc2[4][2];
    #pragma unroll
    for (int i = 0; i < 4; i++) { acc2[i][0] = 0ull; acc2[i][1] = 0ull; }
    int tb = (tid & 15) * 4;
    int th = (tid >> 4) * 4;
    int lr = tid >> 4, lc = (tid & 15) * 4;
    __syncthreads();
    for (int k0 = 0; k0 < 128; k0 += 16) {
        *(float4*)&sw[lr][lc] = *(const float4*)(W + (size_t)(kb + k0 + lr)*NCOL + n0 + lc);
        __syncthreads();
        #pragma unroll
        for (int kk = 0; kk < 16; kk++) {
            float4 a = *(float4*)&sp[k0+kk][tb];
            u64 b0 = *(u64*)&sw[kk][th];
            u64 b1 = *(u64*)&sw[kk][th+2];
            float av[4] = {a.x, a.y, a.z, a.w};
            #pragma unroll
            for (int i = 0; i < 4; i++) {
                u64 ad = dup2(av[i]);
                acc2[i][0] = ffma2(ad, b0, acc2[i][0]);
                acc2[i][1] = ffma2(ad, b1, acc2[i][1]);
            }
        }
        __syncthreads();
    }
    #pragma unroll
    for (int i = 0; i < 4; i++) {
        int c = tb + i;
        float2 f0 = up2(acc2[i][0]), f1 = up2(acc2[i][1]);
        float o[4] = {f0.x, f0.y, f1.x, f1.y};
        #pragma unroll
        for (int j = 0; j < 4; j++) {
            if (blockIdx.y == 0) o[j] += bias[n0 + th + j];
            atomicAdd(vout + (size_t)c*NCOL + n0 + th + j, o[j]);
        }
    }
}

// ---------------- layernorm ----------------
__global__ void k_ln(const float* __restrict__ lng, const float* __restrict__ lnb,
                     float* __restrict__ out) {
    int c = blockIdx.x, t = threadIdx.x;
    __shared__ float sh[34];
    float v0 = g_h2[c*HID + t], v1 = g_h2[c*HID + 256 + t];
    int lane = t & 31, w = t >> 5;
    float s = v0 + v1;
    #pragma unroll
    for (int off = 16; off; off >>= 1) s += __shfl_xor_sync(~0u, s, off);
    if (lane == 0) sh[w] = s;
    __syncthreads();
    if (w == 0) {
        float tot = (t < 8) ? sh[t] : 0.f;
        #pragma unroll
        for (int off = 4; off; off >>= 1) tot += __shfl_xor_sync(~0u, tot, off);
        if (t == 0) sh[32] = tot;
    }
    __syncthreads();
    float mu = sh[32] * (1.f/512.f);
    float d0 = v0 - mu, d1 = v1 - mu;
    float q = d0*d0 + d1*d1;
    #pragma unroll
    for (int off = 16; off; off >>= 1) q += __shfl_xor_sync(~0u, q, off);
    if (lane == 0) sh[w] = q;
    __syncthreads();
    if (w == 0) {
        float tot = (t < 8) ? sh[t] : 0.f;
        #pragma unroll
        for (int off = 4; off; off >>= 1) tot += __shfl_xor_sync(~0u, tot, off);
        if (t == 0) sh[33] = tot;
    }
    __syncthreads();
    float inv = rsqrtf(sh[33] * (1.f/512.f) + 1e-5f);
    float r0 = d0*inv*lng[t]     + lnb[t];
    float r1 = d1*inv*lng[256+t] + lnb[256+t];
    g_int[c*HID + t]       = r0;
    g_int[c*HID + 256 + t] = r1;
    out[64 + c*HID + t]       = r0;
    out[64 + c*HID + 256 + t] = r1;
}

// ---------------- per-cell affinity head (8 blocks/cell, fused sigmoid) ----------------
__global__ void __launch_bounds__(64) k_aff(const float* __restrict__ Aw1,
                                            const float* __restrict__ Ab1,
                                            const float* __restrict__ Aw2,
                                            const float* __restrict__ Ab2,
                                            float* __restrict__ out) {
    int c = blockIdx.x;
    int k = blockIdx.y * 64 + threadIdx.x;
    __shared__ float a[HID];
    __shared__ float red[2];
    for (int j = threadIdx.x; j < HID; j += 64) a[j] = g_int[c*HID + j];
    __syncthreads();
    float acc = Ab1[c*HID + k];
    const float* W = Aw1 + (size_t)c*HID*HID + k;
    #pragma unroll 8
    for (int j = 0; j < HID; j++) acc += a[j] * W[(size_t)j*HID];
    float part = fmaxf(acc, 0.f) * Aw2[c*HID + k];
    int lane = threadIdx.x & 31, w = threadIdx.x >> 5;
    #pragma unroll
    for (int off = 16; off; off >>= 1) part += __shfl_xor_sync(~0u, part, off);
    if (lane == 0) red[w] = part;
    __syncthreads();
    if (threadIdx.x == 0) {
        atomicAdd(&g_affacc[c], red[0] + red[1]);
        __threadfence();
        int done = atomicAdd(&g_affcnt[c], 1);
        if (done == 7) {
            float s = *((volatile float*)&g_affacc[c]);
            out[c] = 1.f / (1.f + expf(-(s + Ab2[c])));
        }
    }
}

extern "C" void kernel_launch(void* const* d_in, const int* in_sizes, int n_in,
                              void* d_out, int out_size) {
    const float* x       = (const float*)d_in[0];
    const int*   ei      = (const int*)  d_in[1];
    const float* gene_W  = (const float*)d_in[3];
    const float* gene_b  = (const float*)d_in[4];
    const int*   cell_ids= (const int*)  d_in[5];
    const int*   counts  = (const int*)  d_in[7];
    const float* Wq = (const float*)d_in[8],  *bq = (const float*)d_in[9];
    const float* Wk = (const float*)d_in[10], *bk = (const float*)d_in[11];
    const float* Wv = (const float*)d_in[12], *bv = (const float*)d_in[13];
    const float* Wo = (const float*)d_in[14], *bo = (const float*)d_in[15];
    const float* Wi1= (const float*)d_in[16], *bi1= (const float*)d_in[17];
    const float* Wi2= (const float*)d_in[18], *bi2= (const float*)d_in[19];
    const float* lng= (const float*)d_in[20], *lnb= (const float*)d_in[21];
    const float* Aw1= (const float*)d_in[22], *Ab1= (const float*)d_in[23];
    const float* Aw2= (const float*)d_in[24], *Ab2= (const float*)d_in[25];
    float* out = (float*)d_out;

    cudaFuncSetAttribute(k_attn_mma, cudaFuncAttributeMaxDynamicSharedMemorySize, ATTN_SMEM);
    cudaFuncSetAttribute(k_qkv_mma, cudaFuncAttributeMaxDynamicSharedMemorySize, QKV_SMEM);
    cudaFuncSetAttribute(k_gene_mma, cudaFuncAttributeMaxDynamicSharedMemorySize, GENE_SMEM);

    k_prep <<<1024, 256>>>(counts, Wq, Wk, Wv);
    k_edges<<<(NEDGES*32)/256, 256>>>(x, ei);
    k_pool <<<NB, 128>>>(x);
    k_gene_mma<<<dim3(NG, 8), 256, GENE_SMEM>>>(gene_W, gene_b);
    k_qkv_mma<<<dim3(MTILES, 8), 256, QKV_SMEM>>>(bq, bk, bv);
    k_attn_mma<<<dim3(NG, 8), 128, ATTN_SMEM>>>(cell_ids, counts);
    k_vm2<512,  512, 0, 0><<<dim3(8, 4),  256>>>(Wo,  bo);
    k_vm2<512, 1024, 0, 1><<<dim3(16, 4), 256>>>(Wi1, bi1);
    k_vm2<1024, 512, 1, 2><<<dim3(8, 8),  256>>>(Wi2, bi2);
    k_ln  <<<NC, 256>>>(lng, lnb, out);
    k_aff <<<dim3(NC, 8), 64>>>(Aw1, Ab1, Aw2, Ab2, out);
}